// round 4
// baseline (speedup 1.0000x reference)
#include <cuda_runtime.h>
#include <math.h>

// ---------------------------------------------------------------------------
// Problem dims
// ---------------------------------------------------------------------------
#define T_STEPS 16
#define B_SZ    32
#define C_IN    2048
#define MEM_SZ  512
#define N_CLS   8
#define C_CAM   1000
#define HW      49          // 7x7
#define PADHW   81          // 9x9 padded
#define KX      (C_IN*9)    // 18432  (x part of K)
#define KH      (MEM_SZ*9)  // 4608   (h part of K)
#define NSTRIDE ((C_IN+MEM_SZ)*9) // 23040, row stride of main weights
#define MBIG    (T_STEPS*B_SZ*HW) // 25088
#define MSTEP   (B_SZ*HW)         // 1568
#define TB      (T_STEPS*B_SZ)    // 512

// ---------------------------------------------------------------------------
// Static device scratch (allocation-free rule: __device__ globals)
// ---------------------------------------------------------------------------
__device__ float g_xpad[TB * C_IN * PADHW];       // padded (then attention-scaled) input, ~340MB
__device__ float g_preS0[MBIG];                   // attention gate pre-acts (x part): fi
__device__ float g_preS1[MBIG];                   // c
__device__ float g_preS2[MBIG];                   // o
__device__ float g_attmap[MBIG];                  // CAM softmax map
__device__ float g_s[MBIG];                       // softmax(a) per step
__device__ float g_a[B_SZ * HW];                  // attention state a
__device__ float g_cs[B_SZ * HW];                 // attention cell state
__device__ float g_pooled[TB * C_IN];
__device__ float g_logits[TB * C_CAM];
__device__ int   g_idx[TB];
__device__ float g_cam[TB * HW];
__device__ float g_preM0[MBIG * MEM_SZ];          // main gate pre-acts (x_att part), 51MB each
__device__ float g_preM1[MBIG * MEM_SZ];
__device__ float g_preM2[MBIG * MEM_SZ];
__device__ float g_hpad[B_SZ * MEM_SZ * PADHW];   // padded h state
__device__ float g_cstate[MSTEP * MEM_SZ];        // main cell state [m][n]
__device__ float g_hpre0[MSTEP * MEM_SZ];         // per-step h-part GEMM out
__device__ float g_hpre1[MSTEP * MEM_SZ];
__device__ float g_hpre2[MSTEP * MEM_SZ];

__device__ __forceinline__ float sigmoidf_(float x) { return 1.0f / (1.0f + expf(-x)); }

// ---------------------------------------------------------------------------
// Zero recurrent states (every call -> deterministic)
// ---------------------------------------------------------------------------
__global__ void zero_states() {
    int i = blockIdx.x * 256 + threadIdx.x;
    if (i < B_SZ * MEM_SZ * PADHW) g_hpad[i] = 0.f;
    if (i < MSTEP * MEM_SZ)        g_cstate[i] = 0.f;
    if (i < B_SZ * HW)             { g_a[i] = 0.f; g_cs[i] = 0.f; }
}

// ---------------------------------------------------------------------------
// Build zero-padded input: xpad[(tb*C + c)*81 + ph*9+pw]
// ---------------------------------------------------------------------------
__global__ void pad_x(const float* __restrict__ x) {
    int lin = blockIdx.x * 256 + threadIdx.x;
    const int TOT = TB * C_IN * PADHW;
    if (lin >= TOT) return;
    int p  = lin % PADHW;
    int rc = lin / PADHW;            // tb*C_IN + c
    int ph = p / 9, pw = p % 9;
    float v = 0.f;
    if (ph >= 1 && ph <= 7 && pw >= 1 && pw <= 7)
        v = x[rc * HW + (ph - 1) * 7 + (pw - 1)];
    g_xpad[lin] = v;
}

// ---------------------------------------------------------------------------
// Attention-gate x contributions: preS[g][m] = sum_k xrow[k] * Ws_g[k], K=18432
// one block per m=(t,b,hw)
// ---------------------------------------------------------------------------
__global__ void preS_kernel(const float* __restrict__ Wfi,
                            const float* __restrict__ Wc,
                            const float* __restrict__ Wo) {
    int m   = blockIdx.x;
    int tb  = m / HW, hw = m % HW;
    int h   = hw / 7, w = hw % 7;
    int tid = threadIdx.x;
    const float* ap = &g_xpad[(size_t)tb * C_IN * PADHW];
    float a0 = 0.f, a1 = 0.f, a2 = 0.f;
    for (int k = tid; k < KX; k += 256) {
        int c = k / 9, r = k % 9;
        int kh = r / 3, kw = r % 3;
        float v = ap[c * PADHW + (h + kh) * 9 + (w + kw)];
        a0 += v * Wfi[k];
        a1 += v * Wc[k];
        a2 += v * Wo[k];
    }
    __shared__ float red[256];
    red[tid] = a0; __syncthreads();
    for (int s = 128; s > 0; s >>= 1) { if (tid < s) red[tid] += red[tid + s]; __syncthreads(); }
    if (tid == 0) g_preS0[m] = red[0];
    __syncthreads();
    red[tid] = a1; __syncthreads();
    for (int s = 128; s > 0; s >>= 1) { if (tid < s) red[tid] += red[tid + s]; __syncthreads(); }
    if (tid == 0) g_preS1[m] = red[0];
    __syncthreads();
    red[tid] = a2; __syncthreads();
    for (int s = 128; s > 0; s >>= 1) { if (tid < s) red[tid] += red[tid + s]; __syncthreads(); }
    if (tid == 0) g_preS2[m] = red[0];
}

// ---------------------------------------------------------------------------
// CAM pipeline
// ---------------------------------------------------------------------------
__global__ void pooled_kernel(const float* __restrict__ x) {
    int lin = blockIdx.x * 256 + threadIdx.x;   // tb*C_IN + c
    if (lin >= TB * C_IN) return;
    const float* p = x + (size_t)lin * HW;
    float s = 0.f;
    #pragma unroll
    for (int i = 0; i < HW; i++) s += p[i];
    g_pooled[lin] = s * (1.0f / 49.0f);
}

__global__ void cam_logits_kernel(const float* __restrict__ W_cam) {
    int gw   = blockIdx.x * 4 + (threadIdx.x >> 5);
    int lane = threadIdx.x & 31;
    if (gw >= TB * C_CAM) return;
    int tb = gw / C_CAM, j = gw % C_CAM;
    const float* p  = &g_pooled[tb * C_IN];
    const float* wr = &W_cam[(size_t)j * C_IN];
    float acc = 0.f;
    for (int c = lane; c < C_IN; c += 32) acc += p[c] * wr[c];
    #pragma unroll
    for (int o = 16; o > 0; o >>= 1) acc += __shfl_down_sync(0xffffffffu, acc, o);
    if (lane == 0) g_logits[gw] = acc;
}

__global__ void argmax_kernel() {
    int tb = blockIdx.x, tid = threadIdx.x;
    float best = -INFINITY; int bi = 0;
    for (int j = tid; j < C_CAM; j += 256) {
        float v = g_logits[tb * C_CAM + j];
        if (v > best) { best = v; bi = j; }
    }
    __shared__ float sv[256]; __shared__ int si[256];
    sv[tid] = best; si[tid] = bi; __syncthreads();
    for (int s = 128; s > 0; s >>= 1) {
        if (tid < s) {
            float v2 = sv[tid + s]; int i2 = si[tid + s];
            if (v2 > sv[tid] || (v2 == sv[tid] && i2 < si[tid])) { sv[tid] = v2; si[tid] = i2; }
        }
        __syncthreads();
    }
    if (tid == 0) g_idx[tb] = si[0];
}

__global__ void cam_kernel(const float* __restrict__ x, const float* __restrict__ W_cam) {
    int gw   = blockIdx.x * 8 + (threadIdx.x >> 5);
    int lane = threadIdx.x & 31;
    if (gw >= TB * HW) return;
    int tb = gw / HW, hw = gw % HW;
    const float* wsel = &W_cam[(size_t)g_idx[tb] * C_IN];
    const float* xp   = x + (size_t)tb * C_IN * HW + hw;
    float acc = 0.f;
    for (int c = lane; c < C_IN; c += 32) acc += wsel[c] * xp[(size_t)c * HW];
    #pragma unroll
    for (int o = 16; o > 0; o >>= 1) acc += __shfl_down_sync(0xffffffffu, acc, o);
    if (lane == 0) g_cam[gw] = acc;
}

__global__ void cam_softmax_kernel() {
    int tb = blockIdx.x, tid = threadIdx.x; // 64 threads
    __shared__ float v[HW]; __shared__ float red[64];
    if (tid < HW) v[tid] = g_cam[tb * HW + tid];
    __syncthreads();
    float m = (tid < HW) ? v[tid] : -INFINITY;
    red[tid] = m; __syncthreads();
    for (int s = 32; s > 0; s >>= 1) { if (tid < s) red[tid] = fmaxf(red[tid], red[tid + s]); __syncthreads(); }
    float mx = red[0]; __syncthreads();
    float e = (tid < HW) ? expf(v[tid] - mx) : 0.f;
    red[tid] = e; __syncthreads();
    for (int s = 32; s > 0; s >>= 1) { if (tid < s) red[tid] += red[tid + s]; __syncthreads(); }
    if (tid < HW) g_attmap[tb * HW + tid] = e / red[0];
}

// ---------------------------------------------------------------------------
// Attention recurrence, one step (32 blocks x 64 threads)
// ---------------------------------------------------------------------------
__global__ void att_step(int t,
                         const float* __restrict__ Wfi, const float* __restrict__ Wc,
                         const float* __restrict__ Wo,
                         const float* __restrict__ bfi, const float* __restrict__ bc,
                         const float* __restrict__ bo) {
    int b = blockIdx.x, tid = threadIdx.x;
    __shared__ float ap[HW]; __shared__ float av[HW]; __shared__ float red[64];
    if (tid < HW) ap[tid] = g_a[b * HW + tid];
    __syncthreads();
    if (tid < HW) {
        int h = tid / 7, w = tid % 7;
        float efi = 0.f, ec = 0.f, eo = 0.f;
        #pragma unroll
        for (int kh = 0; kh < 3; kh++)
            #pragma unroll
            for (int kw = 0; kw < 3; kw++) {
                int hh = h + kh - 1, ww = w + kw - 1;
                if (hh >= 0 && hh < 7 && ww >= 0 && ww < 7) {
                    float aval = ap[hh * 7 + ww];
                    int off = KX + kh * 3 + kw;
                    efi += aval * Wfi[off];
                    ec  += aval * Wc[off];
                    eo  += aval * Wo[off];
                }
            }
        int base = (t * B_SZ + b) * HW + tid;
        float fi = sigmoidf_(g_preS0[base] + efi + bfi[0]);
        float o  = sigmoidf_(g_preS2[base] + eo + bo[0]);
        float cc = tanhf(g_preS1[base] + ec + bc[0]);
        float cs = fi * g_cs[b * HW + tid] + (1.0f - fi) * cc;
        g_cs[b * HW + tid] = cs;
        float an = o * tanhf(cs) * g_attmap[base];
        g_a[b * HW + tid] = an;
        av[tid] = an;
    }
    __syncthreads();
    float m = (tid < HW) ? av[tid] : -INFINITY;
    red[tid] = m; __syncthreads();
    for (int s = 32; s > 0; s >>= 1) { if (tid < s) red[tid] = fmaxf(red[tid], red[tid + s]); __syncthreads(); }
    float mx = red[0]; __syncthreads();
    float e = (tid < HW) ? expf(av[tid] - mx) : 0.f;
    red[tid] = e; __syncthreads();
    for (int s = 32; s > 0; s >>= 1) { if (tid < s) red[tid] += red[tid + s]; __syncthreads(); }
    if (tid < HW) g_s[(t * B_SZ + b) * HW + tid] = e / red[0];
}

// ---------------------------------------------------------------------------
// x_att = x * softmax(a): scale padded input in place (borders remain 0)
// ---------------------------------------------------------------------------
__global__ void scale_x() {
    int lin = blockIdx.x * 256 + threadIdx.x;
    const int TOT = TB * C_IN * HW;
    if (lin >= TOT) return;
    int hw = lin % HW;
    int rc = lin / HW;             // tb*C_IN + c
    int tb = rc / C_IN;
    float sc = g_s[tb * HW + hw];
    int p = (hw / 7 + 1) * 9 + (hw % 7 + 1);
    g_xpad[(size_t)rc * PADHW + p] *= sc;
}

// ---------------------------------------------------------------------------
// Implicit-GEMM conv: O_g[m*512+n] = sum_k A[m,k] * W_g[n*nstride + kbase + k]
// A gathered from padded buffer: rows (tb*C + c), k = (c, kh, kw)
// Tiles: 128x64x16, 256 threads, 8x4 per thread.
// ---------------------------------------------------------------------------
#define GBM 128
#define GBN 64
#define GBK 16

__global__ __launch_bounds__(256) void conv_gemm(
    const float* __restrict__ Apad, int C, int M, int K,
    const float* __restrict__ W0, const float* __restrict__ W1, const float* __restrict__ W2,
    int nstride, int kbase,
    float* __restrict__ O0, float* __restrict__ O1, float* __restrict__ O2) {

    const float* Wg = (blockIdx.z == 0) ? W0 : (blockIdx.z == 1 ? W1 : W2);
    float*       Og = (blockIdx.z == 0) ? O0 : (blockIdx.z == 1 ? O1 : O2);

    __shared__ float As[GBK][GBM];
    __shared__ float Bs[GBK][GBN + 4];

    int m0  = blockIdx.x * GBM;
    int n0  = blockIdx.y * GBN;
    int tid = threadIdx.x;
    int tx  = tid & 15;        // n dir
    int ty  = tid >> 4;        // m dir

    // A-load geometry: fixed per thread
    int ml = tid & 127;
    int khalf = tid >> 7;      // 0/1
    int m = m0 + ml;
    bool mvalid = (m < M);
    int abase = 0;
    int hh = 0, ww = 0;
    if (mvalid) {
        int tb = m / HW, hw = m % HW;
        hh = hw / 7; ww = hw % 7;
        abase = tb * C * PADHW;
    }
    // B-load geometry: fixed per thread
    int bk = tid & 15;
    int bn = tid >> 4;          // 0..15, + 16*i

    float acc[8][4];
    #pragma unroll
    for (int i = 0; i < 8; i++)
        #pragma unroll
        for (int j = 0; j < 4; j++) acc[i][j] = 0.f;

    for (int k0 = 0; k0 < K; k0 += GBK) {
        // ---- load A tile (8 elems/thread, kk = khalf + 2i) ----
        #pragma unroll
        for (int i = 0; i < 8; i++) {
            int kk = khalf + 2 * i;
            float v = 0.f;
            if (mvalid) {
                int k = k0 + kk;
                int c = k / 9, r = k % 9;
                v = Apad[abase + c * PADHW + (hh + r / 3) * 9 + (ww + r % 3)];
            }
            As[kk][ml] = v;
        }
        // ---- load B tile (4 elems/thread) ----
        #pragma unroll
        for (int i = 0; i < 4; i++) {
            int nl = bn + 16 * i;
            Bs[bk][nl] = Wg[(size_t)(n0 + nl) * nstride + kbase + k0 + bk];
        }
        __syncthreads();
        // ---- compute ----
        #pragma unroll
        for (int kk = 0; kk < GBK; kk++) {
            float4 a0 = *(const float4*)&As[kk][ty * 8];
            float4 a1 = *(const float4*)&As[kk][ty * 8 + 4];
            float4 bb = *(const float4*)&Bs[kk][tx * 4];
            float ar[8] = {a0.x, a0.y, a0.z, a0.w, a1.x, a1.y, a1.z, a1.w};
            float br[4] = {bb.x, bb.y, bb.z, bb.w};
            #pragma unroll
            for (int i = 0; i < 8; i++)
                #pragma unroll
                for (int j = 0; j < 4; j++) acc[i][j] += ar[i] * br[j];
        }
        __syncthreads();
    }
    // ---- store ----
    #pragma unroll
    for (int i = 0; i < 8; i++) {
        int mm = m0 + ty * 8 + i;
        if (mm < M) {
            float4 v = make_float4(acc[i][0], acc[i][1], acc[i][2], acc[i][3]);
            *(float4*)&Og[(size_t)mm * MEM_SZ + n0 + tx * 4] = v;
        }
    }
}

// ---------------------------------------------------------------------------
// Main gate update, one step
// ---------------------------------------------------------------------------
__global__ void gate_step(int t, const float* __restrict__ bfi,
                          const float* __restrict__ bc, const float* __restrict__ bo) {
    int lin = blockIdx.x * 256 + threadIdx.x;
    if (lin >= MSTEP * MEM_SZ) return;
    int n = lin & (MEM_SZ - 1);
    int m = lin >> 9;            // MEM_SZ = 512
    int b = m / HW, hw = m % HW;
    size_t bigOff = ((size_t)t * MSTEP + m) * MEM_SZ + n;
    float pfi = g_preM0[bigOff] + g_hpre0[lin] + bfi[n];
    float pc  = g_preM1[bigOff] + g_hpre1[lin] + bc[n];
    float po  = g_preM2[bigOff] + g_hpre2[lin] + bo[n];
    float fi = sigmoidf_(pfi);
    float o  = sigmoidf_(po);
    float cn = fi * g_cstate[lin] + (1.0f - fi) * tanhf(pc);
    g_cstate[lin] = cn;
    float h = o * tanhf(cn);
    g_hpad[(size_t)(b * MEM_SZ + n) * PADHW + (hw / 7 + 1) * 9 + (hw % 7 + 1)] = h;
}

// ---------------------------------------------------------------------------
// Final: feats = mean_hw(h); logits = feats @ W_fc^T + b_fc
// ---------------------------------------------------------------------------
__global__ void final_kernel(const float* __restrict__ W_fc, const float* __restrict__ b_fc,
                             float* __restrict__ logitsOut, float* __restrict__ featsOut) {
    int b = blockIdx.x, n = threadIdx.x; // 512 threads
    const float* hp = &g_hpad[(size_t)(b * MEM_SZ + n) * PADHW];
    float s = 0.f;
    #pragma unroll
    for (int hh = 1; hh <= 7; hh++)
        #pragma unroll
        for (int ww = 1; ww <= 7; ww++) s += hp[hh * 9 + ww];
    float f = s * (1.0f / 49.0f);
    __shared__ float fs[MEM_SZ];
    fs[n] = f;
    if (featsOut) featsOut[b * MEM_SZ + n] = f;
    __syncthreads();
    if (n < N_CLS && logitsOut) {
        float acc = b_fc[n];
        for (int k = 0; k < MEM_SZ; k++) acc += fs[k] * W_fc[n * MEM_SZ + k];
        logitsOut[b * N_CLS + n] = acc;
    }
}

// ---------------------------------------------------------------------------
// Host launcher
// ---------------------------------------------------------------------------
extern "C" void kernel_launch(void* const* d_in, const int* in_sizes, int n_in,
                              void* d_out, int out_size) {
    const float* x     = (const float*)d_in[0];
    const float* W_fi  = (const float*)d_in[1];
    const float* b_fi  = (const float*)d_in[2];
    const float* W_c   = (const float*)d_in[3];
    const float* b_c   = (const float*)d_in[4];
    const float* W_o   = (const float*)d_in[5];
    const float* b_o   = (const float*)d_in[6];
    const float* Ws_fi = (const float*)d_in[7];
    const float* bs_fi = (const float*)d_in[8];
    const float* Ws_c  = (const float*)d_in[9];
    const float* bs_c  = (const float*)d_in[10];
    const float* Ws_o  = (const float*)d_in[11];
    const float* bs_o  = (const float*)d_in[12];
    const float* W_cam = (const float*)d_in[13];
    const float* W_fc  = (const float*)d_in[14];
    const float* b_fc  = (const float*)d_in[15];

    float* xpad; cudaGetSymbolAddress((void**)&xpad, g_xpad);
    float* hpad; cudaGetSymbolAddress((void**)&hpad, g_hpad);
    float* pm0;  cudaGetSymbolAddress((void**)&pm0, g_preM0);
    float* pm1;  cudaGetSymbolAddress((void**)&pm1, g_preM1);
    float* pm2;  cudaGetSymbolAddress((void**)&pm2, g_preM2);
    float* hp0;  cudaGetSymbolAddress((void**)&hp0, g_hpre0);
    float* hp1;  cudaGetSymbolAddress((void**)&hp1, g_hpre1);
    float* hp2;  cudaGetSymbolAddress((void**)&hp2, g_hpre2);

    float* outF = (float*)d_out;
    float* lp = nullptr; float* fp = nullptr;
    if (out_size >= B_SZ * N_CLS + B_SZ * MEM_SZ) { lp = outF; fp = outF + B_SZ * N_CLS; }
    else if (out_size == B_SZ * MEM_SZ)           { fp = outF; }
    else                                          { lp = outF; }

    // 1. reset recurrent state
    zero_states<<<(B_SZ * MEM_SZ * PADHW + 255) / 256, 256>>>();
    // 2. pad input
    pad_x<<<(TB * C_IN * PADHW + 255) / 256, 256>>>(x);
    // 3. attention-gate x contributions (all t)
    preS_kernel<<<MBIG, 256>>>(Ws_fi, Ws_c, Ws_o);
    // 4. CAM pipeline (all t)
    pooled_kernel<<<(TB * C_IN + 255) / 256, 256>>>(x);
    cam_logits_kernel<<<(TB * C_CAM + 3) / 4, 128>>>(W_cam);
    argmax_kernel<<<TB, 256>>>();
    cam_kernel<<<(TB * HW + 7) / 8, 256>>>(x, W_cam);
    cam_softmax_kernel<<<TB, 64>>>();
    // 5. sequential attention recurrence (cheap)
    for (int t = 0; t < T_STEPS; t++)
        att_step<<<B_SZ, 64>>>(t, Ws_fi, Ws_c, Ws_o, bs_fi, bs_c, bs_o);
    // 6. apply attention scaling in place
    scale_x<<<(TB * C_IN * HW + 255) / 256, 256>>>();
    // 7. giant parallel GEMM: x_att conv contributions for all t, 3 gates
    {
        dim3 grid((MBIG + GBM - 1) / GBM, MEM_SZ / GBN, 3);
        conv_gemm<<<grid, 256>>>(xpad, C_IN, MBIG, KX,
                                 W_fi, W_c, W_o, NSTRIDE, 0, pm0, pm1, pm2);
    }
    // 8. sequential main recurrence: h-part GEMM + gates per step
    for (int t = 0; t < T_STEPS; t++) {
        dim3 grid((MSTEP + GBM - 1) / GBM, MEM_SZ / GBN, 3);
        conv_gemm<<<grid, 256>>>(hpad, MEM_SZ, MSTEP, KH,
                                 W_fi, W_c, W_o, NSTRIDE, KX, hp0, hp1, hp2);
        gate_step<<<(MSTEP * MEM_SZ + 255) / 256, 256>>>(t, b_fi, b_c, b_o);
    }
    // 9. final pooling + FC head
    final_kernel<<<B_SZ, MEM_SZ>>>(W_fc, b_fc, lp, fp);
}

// round 5
// speedup vs baseline: 3.9753x; 3.9753x over previous
#include <cuda_runtime.h>
#include <math.h>
#include <stdint.h>

// ---------------------------------------------------------------------------
// Problem dims
// ---------------------------------------------------------------------------
#define T_STEPS 16
#define B_SZ    32
#define C_IN    2048
#define MEM_SZ  512
#define N_CLS   8
#define C_CAM   1000
#define HW      49          // 7x7
#define PADHW   81          // 9x9 padded
#define KX      (C_IN*9)    // 18432  (x part of K)
#define KH      (MEM_SZ*9)  // 4608   (h part of K)
#define NSTRIDE ((C_IN+MEM_SZ)*9) // 23040, row stride of main weights
#define MBIG    (T_STEPS*B_SZ*HW) // 25088
#define MSTEP   (B_SZ*HW)         // 1568
#define TB      (T_STEPS*B_SZ)    // 512
#define NFUSED  (3*MEM_SZ)        // 1536

// ---------------------------------------------------------------------------
// Static device scratch
// ---------------------------------------------------------------------------
__device__ float g_xpad[TB * C_IN * PADHW];        // padded, tf32-rounded input (~340MB)
__device__ float g_wr[3 * MEM_SZ * NSTRIDE];       // tf32-rounded main weights (141MB)
__device__ float g_preS0[MBIG];
__device__ float g_preS1[MBIG];
__device__ float g_preS2[MBIG];
__device__ float g_attmap[MBIG];
__device__ float g_s[MBIG];
__device__ float g_a[B_SZ * HW];
__device__ float g_cs[B_SZ * HW];
__device__ float g_pooled[TB * C_IN];
__device__ float g_logits[TB * C_CAM];
__device__ int   g_idx[TB];
__device__ float g_cam[TB * HW];
__device__ float g_preM[(size_t)MBIG * NFUSED];    // fused gate pre-acts (x part), 154MB
__device__ float g_hpre[(size_t)MSTEP * NFUSED];   // per-step h-part GEMM out
__device__ float g_hpad[B_SZ * MEM_SZ * PADHW];    // padded, tf32-rounded h state
__device__ float g_cstate[MSTEP * MEM_SZ];

__device__ __forceinline__ float sigmoidf_(float x) { return 1.0f / (1.0f + expf(-x)); }
__device__ __forceinline__ float rna_tf32(float x) {
    unsigned u;
    asm("cvt.rna.tf32.f32 %0, %1;" : "=r"(u) : "f"(x));
    return __uint_as_float(u);
}

// ---------------------------------------------------------------------------
// Zero recurrent states
// ---------------------------------------------------------------------------
__global__ void zero_states() {
    int i = blockIdx.x * 256 + threadIdx.x;
    if (i < B_SZ * MEM_SZ * PADHW) g_hpad[i] = 0.f;
    if (i < MSTEP * MEM_SZ)        g_cstate[i] = 0.f;
    if (i < B_SZ * HW)             { g_a[i] = 0.f; g_cs[i] = 0.f; }
}

// ---------------------------------------------------------------------------
// Build zero-padded, tf32-rounded input
// ---------------------------------------------------------------------------
__global__ void pad_x(const float* __restrict__ x) {
    int lin = blockIdx.x * 256 + threadIdx.x;
    const int TOT = TB * C_IN * PADHW;
    if (lin >= TOT) return;
    int p  = lin % PADHW;
    int rc = lin / PADHW;
    int ph = p / 9, pw = p % 9;
    float v = 0.f;
    if (ph >= 1 && ph <= 7 && pw >= 1 && pw <= 7)
        v = rna_tf32(x[rc * HW + (ph - 1) * 7 + (pw - 1)]);
    g_xpad[lin] = v;
}

// ---------------------------------------------------------------------------
// Round main weights to tf32 into fused buffer [gate][512][23040]
// ---------------------------------------------------------------------------
__global__ void round_weights(const float* __restrict__ W0,
                              const float* __restrict__ W1,
                              const float* __restrict__ W2) {
    size_t i = (size_t)blockIdx.x * 256 + threadIdx.x;
    const size_t S = (size_t)MEM_SZ * NSTRIDE;
    if (i >= S) return;
    g_wr[i]         = rna_tf32(W0[i]);
    g_wr[S + i]     = rna_tf32(W1[i]);
    g_wr[2 * S + i] = rna_tf32(W2[i]);
}

// ---------------------------------------------------------------------------
// Attention-gate x contributions (fp32, reads rounded xpad - negligible error)
// ---------------------------------------------------------------------------
__global__ void preS_kernel(const float* __restrict__ Wfi,
                            const float* __restrict__ Wc,
                            const float* __restrict__ Wo) {
    int m   = blockIdx.x;
    int tb  = m / HW, hw = m % HW;
    int h   = hw / 7, w = hw % 7;
    int tid = threadIdx.x;
    const float* ap = &g_xpad[(size_t)tb * C_IN * PADHW];
    float a0 = 0.f, a1 = 0.f, a2 = 0.f;
    for (int k = tid; k < KX; k += 256) {
        int c = k / 9, r = k % 9;
        int kh = r / 3, kw = r % 3;
        float v = ap[c * PADHW + (h + kh) * 9 + (w + kw)];
        a0 += v * Wfi[k];
        a1 += v * Wc[k];
        a2 += v * Wo[k];
    }
    __shared__ float red[256];
    red[tid] = a0; __syncthreads();
    for (int s = 128; s > 0; s >>= 1) { if (tid < s) red[tid] += red[tid + s]; __syncthreads(); }
    if (tid == 0) g_preS0[m] = red[0];
    __syncthreads();
    red[tid] = a1; __syncthreads();
    for (int s = 128; s > 0; s >>= 1) { if (tid < s) red[tid] += red[tid + s]; __syncthreads(); }
    if (tid == 0) g_preS1[m] = red[0];
    __syncthreads();
    red[tid] = a2; __syncthreads();
    for (int s = 128; s > 0; s >>= 1) { if (tid < s) red[tid] += red[tid + s]; __syncthreads(); }
    if (tid == 0) g_preS2[m] = red[0];
}

// ---------------------------------------------------------------------------
// CAM pipeline (uses raw x)
// ---------------------------------------------------------------------------
__global__ void pooled_kernel(const float* __restrict__ x) {
    int lin = blockIdx.x * 256 + threadIdx.x;
    if (lin >= TB * C_IN) return;
    const float* p = x + (size_t)lin * HW;
    float s = 0.f;
    #pragma unroll
    for (int i = 0; i < HW; i++) s += p[i];
    g_pooled[lin] = s * (1.0f / 49.0f);
}

__global__ void cam_logits_kernel(const float* __restrict__ W_cam) {
    int gw   = blockIdx.x * 4 + (threadIdx.x >> 5);
    int lane = threadIdx.x & 31;
    if (gw >= TB * C_CAM) return;
    int tb = gw / C_CAM, j = gw % C_CAM;
    const float* p  = &g_pooled[tb * C_IN];
    const float* wr = &W_cam[(size_t)j * C_IN];
    float acc = 0.f;
    for (int c = lane; c < C_IN; c += 32) acc += p[c] * wr[c];
    #pragma unroll
    for (int o = 16; o > 0; o >>= 1) acc += __shfl_down_sync(0xffffffffu, acc, o);
    if (lane == 0) g_logits[gw] = acc;
}

__global__ void argmax_kernel() {
    int tb = blockIdx.x, tid = threadIdx.x;
    float best = -INFINITY; int bi = 0;
    for (int j = tid; j < C_CAM; j += 256) {
        float v = g_logits[tb * C_CAM + j];
        if (v > best) { best = v; bi = j; }
    }
    __shared__ float sv[256]; __shared__ int si[256];
    sv[tid] = best; si[tid] = bi; __syncthreads();
    for (int s = 128; s > 0; s >>= 1) {
        if (tid < s) {
            float v2 = sv[tid + s]; int i2 = si[tid + s];
            if (v2 > sv[tid] || (v2 == sv[tid] && i2 < si[tid])) { sv[tid] = v2; si[tid] = i2; }
        }
        __syncthreads();
    }
    if (tid == 0) g_idx[tb] = si[0];
}

__global__ void cam_kernel(const float* __restrict__ x, const float* __restrict__ W_cam) {
    int gw   = blockIdx.x * 8 + (threadIdx.x >> 5);
    int lane = threadIdx.x & 31;
    if (gw >= TB * HW) return;
    int tb = gw / HW, hw = gw % HW;
    const float* wsel = &W_cam[(size_t)g_idx[tb] * C_IN];
    const float* xp   = x + (size_t)tb * C_IN * HW + hw;
    float acc = 0.f;
    for (int c = lane; c < C_IN; c += 32) acc += wsel[c] * xp[(size_t)c * HW];
    #pragma unroll
    for (int o = 16; o > 0; o >>= 1) acc += __shfl_down_sync(0xffffffffu, acc, o);
    if (lane == 0) g_cam[gw] = acc;
}

__global__ void cam_softmax_kernel() {
    int tb = blockIdx.x, tid = threadIdx.x; // 64 threads
    __shared__ float v[HW]; __shared__ float red[64];
    if (tid < HW) v[tid] = g_cam[tb * HW + tid];
    __syncthreads();
    float m = (tid < HW) ? v[tid] : -INFINITY;
    red[tid] = m; __syncthreads();
    for (int s = 32; s > 0; s >>= 1) { if (tid < s) red[tid] = fmaxf(red[tid], red[tid + s]); __syncthreads(); }
    float mx = red[0]; __syncthreads();
    float e = (tid < HW) ? expf(v[tid] - mx) : 0.f;
    red[tid] = e; __syncthreads();
    for (int s = 32; s > 0; s >>= 1) { if (tid < s) red[tid] += red[tid + s]; __syncthreads(); }
    if (tid < HW) g_attmap[tb * HW + tid] = e / red[0];
}

// ---------------------------------------------------------------------------
// Attention recurrence, one step
// ---------------------------------------------------------------------------
__global__ void att_step(int t,
                         const float* __restrict__ Wfi, const float* __restrict__ Wc,
                         const float* __restrict__ Wo,
                         const float* __restrict__ bfi, const float* __restrict__ bc,
                         const float* __restrict__ bo) {
    int b = blockIdx.x, tid = threadIdx.x;
    __shared__ float ap[HW]; __shared__ float av[HW]; __shared__ float red[64];
    if (tid < HW) ap[tid] = g_a[b * HW + tid];
    __syncthreads();
    if (tid < HW) {
        int h = tid / 7, w = tid % 7;
        float efi = 0.f, ec = 0.f, eo = 0.f;
        #pragma unroll
        for (int kh = 0; kh < 3; kh++)
            #pragma unroll
            for (int kw = 0; kw < 3; kw++) {
                int hh = h + kh - 1, ww = w + kw - 1;
                if (hh >= 0 && hh < 7 && ww >= 0 && ww < 7) {
                    float aval = ap[hh * 7 + ww];
                    int off = KX + kh * 3 + kw;
                    efi += aval * Wfi[off];
                    ec  += aval * Wc[off];
                    eo  += aval * Wo[off];
                }
            }
        int base = (t * B_SZ + b) * HW + tid;
        float fi = sigmoidf_(g_preS0[base] + efi + bfi[0]);
        float o  = sigmoidf_(g_preS2[base] + eo + bo[0]);
        float cc = tanhf(g_preS1[base] + ec + bc[0]);
        float cs = fi * g_cs[b * HW + tid] + (1.0f - fi) * cc;
        g_cs[b * HW + tid] = cs;
        float an = o * tanhf(cs) * g_attmap[base];
        g_a[b * HW + tid] = an;
        av[tid] = an;
    }
    __syncthreads();
    float m = (tid < HW) ? av[tid] : -INFINITY;
    red[tid] = m; __syncthreads();
    for (int s = 32; s > 0; s >>= 1) { if (tid < s) red[tid] = fmaxf(red[tid], red[tid + s]); __syncthreads(); }
    float mx = red[0]; __syncthreads();
    float e = (tid < HW) ? expf(av[tid] - mx) : 0.f;
    red[tid] = e; __syncthreads();
    for (int s = 32; s > 0; s >>= 1) { if (tid < s) red[tid] += red[tid + s]; __syncthreads(); }
    if (tid < HW) g_s[(t * B_SZ + b) * HW + tid] = e / red[0];
}

// ---------------------------------------------------------------------------
// x_att = x * softmax(a), re-rounded to tf32
// ---------------------------------------------------------------------------
__global__ void scale_x() {
    int lin = blockIdx.x * 256 + threadIdx.x;
    const int TOT = TB * C_IN * HW;
    if (lin >= TOT) return;
    int hw = lin % HW;
    int rc = lin / HW;
    int tb = rc / C_IN;
    float sc = g_s[tb * HW + hw];
    int p = (hw / 7 + 1) * 9 + (hw % 7 + 1);
    size_t a = (size_t)rc * PADHW + p;
    g_xpad[a] = rna_tf32(g_xpad[a] * sc);
}

// ---------------------------------------------------------------------------
// TF32 tensor-core implicit-GEMM conv.
//   Out[m][gate*512+n] = sum_k A[m,k] * Wr[gate][n0in+n][kbase+k]
// Block tile 128(M) x 128(N) x 32(K), 8 warps (2x4), warp tile 64x32,
// mma.m16n8k8.tf32, 3-stage cp.async pipeline.
// grid: (x = 12 n-blocks [gate*4 + nb], y = m-blocks)  -> L2-friendly waves
// ---------------------------------------------------------------------------
#define AST 132                  // A smem row stride (k-major [32][132])
#define BST 36                   // B smem row stride (n-major [128][36])
#define AE  (32*AST)             // 4224 floats
#define BE  (128*BST)            // 4608 floats
#define STG_ (AE+BE)             // 8832 floats / stage
#define PIPE 3

__global__ __launch_bounds__(256, 2) void conv_gemm_tc(
    const float* __restrict__ Apad, int C, int M, int KT,   // KT = K/32
    const float* __restrict__ Wbase, int kbase,
    float* __restrict__ Out)
{
    extern __shared__ float sm[];
    const int tid  = threadIdx.x;
    const int m0   = blockIdx.y * 128;
    const int gate = blockIdx.x >> 2;
    const int n0in = (blockIdx.x & 3) * 128;
    const float* Wg = Wbase + (size_t)gate * ((size_t)MEM_SZ * NSTRIDE)
                            + (size_t)n0in * NSTRIDE + kbase;

    // ---- A gather geometry (fixed per thread) ----
    const int ml   = tid & 127;
    const int kseg = tid >> 7;            // 0/1 -> k halves
    const int m    = m0 + ml;
    const int am_ok = (m < M) ? 4 : 0;    // cp.async src-size (0 => zero-fill)
    int abase = 0, hh = 0, ww = 0;
    if (m < M) {
        int tb = m / HW, hw = m % HW;
        hh = hw / 7; ww = hw % 7;
        abase = tb * C * PADHW;
    }
    // ---- B load geometry ----
    const int bkk = (tid & 7) * 4;        // k offset, 16B vector
    const int bn  = tid >> 3;             // 0..31 (+32*i)

    // ---- warp/frag geometry ----
    const int lane = tid & 31;
    const int wid  = tid >> 5;
    const int g    = lane >> 2;
    const int cq   = lane & 3;
    const int wmB  = (wid & 1) * 64;
    const int wnB  = (wid >> 1) * 32;

    float acc[4][4][4];
    #pragma unroll
    for (int a = 0; a < 4; a++)
        #pragma unroll
        for (int b = 0; b < 4; b++)
            #pragma unroll
            for (int c = 0; c < 4; c++) acc[a][b][c] = 0.f;

    // ---- cp.async stage loader ----
    auto issue = [&](int s, int kt) {
        float* As_ = sm + s * STG_;
        float* Bs_ = As_ + AE;
        uint32_t aB = (uint32_t)__cvta_generic_to_shared(As_);
        uint32_t bB = (uint32_t)__cvta_generic_to_shared(Bs_);
        int k0 = kt * 32;
        #pragma unroll
        for (int i = 0; i < 16; i++) {
            int kk = kseg * 16 + i;
            int k  = k0 + kk;
            int c  = k / 9;
            int r  = k - 9 * c;
            int dr = r / 3;
            int dc = r - 3 * dr;
            const float* src = Apad + abase + c * PADHW + (hh + dr) * 9 + (ww + dc);
            uint32_t dst = aB + (uint32_t)(kk * AST + ml) * 4u;
            asm volatile("cp.async.ca.shared.global [%0], [%1], 4, %2;\n"
                         :: "r"(dst), "l"(src), "r"(am_ok));
        }
        #pragma unroll
        for (int i = 0; i < 4; i++) {
            int nl = bn + 32 * i;
            const float* src = Wg + (size_t)nl * NSTRIDE + k0 + bkk;
            uint32_t dst = bB + (uint32_t)(nl * BST + bkk) * 4u;
            asm volatile("cp.async.cg.shared.global [%0], [%1], 16;\n"
                         :: "r"(dst), "l"(src));
        }
        asm volatile("cp.async.commit_group;\n");
    };

    // prologue
    #pragma unroll
    for (int s = 0; s < PIPE - 1; s++)
        if (s < KT) issue(s, s);

    for (int kt = 0; kt < KT; kt++) {
        if (kt + 1 < KT) asm volatile("cp.async.wait_group 1;\n");
        else             asm volatile("cp.async.wait_group 0;\n");
        __syncthreads();
        if (kt + PIPE - 1 < KT) issue((kt + PIPE - 1) % PIPE, kt + PIPE - 1);

        const float* As_ = sm + (kt % PIPE) * STG_;
        const float* Bs_ = As_ + AE;

        #pragma unroll
        for (int ks = 0; ks < 4; ks++) {
            int k1 = ks * 8 + cq;
            unsigned af[4][4], bf[4][2];
            #pragma unroll
            for (int mt = 0; mt < 4; mt++) {
                const float* ap = As_ + k1 * AST + wmB + mt * 16 + g;
                af[mt][0] = __float_as_uint(ap[0]);
                af[mt][1] = __float_as_uint(ap[8]);
                af[mt][2] = __float_as_uint(ap[4 * AST]);
                af[mt][3] = __float_as_uint(ap[4 * AST + 8]);
            }
            #pragma unroll
            for (int nt = 0; nt < 4; nt++) {
                const float* bp = Bs_ + (wnB + nt * 8 + g) * BST + k1;
                bf[nt][0] = __float_as_uint(bp[0]);
                bf[nt][1] = __float_as_uint(bp[4]);
            }
            #pragma unroll
            for (int mt = 0; mt < 4; mt++)
                #pragma unroll
                for (int nt = 0; nt < 4; nt++) {
                    asm volatile(
                        "mma.sync.aligned.m16n8k8.row.col.f32.tf32.tf32.f32 "
                        "{%0,%1,%2,%3}, {%4,%5,%6,%7}, {%8,%9}, {%0,%1,%2,%3};\n"
                        : "+f"(acc[mt][nt][0]), "+f"(acc[mt][nt][1]),
                          "+f"(acc[mt][nt][2]), "+f"(acc[mt][nt][3])
                        : "r"(af[mt][0]), "r"(af[mt][1]), "r"(af[mt][2]), "r"(af[mt][3]),
                          "r"(bf[nt][0]), "r"(bf[nt][1]));
                }
        }
        __syncthreads();
    }

    // ---- store (fused N=1536 layout) ----
    const size_t colBase = (size_t)(gate * MEM_SZ + n0in);
    #pragma unroll
    for (int mt = 0; mt < 4; mt++) {
        int r0 = m0 + wmB + mt * 16 + g;
        #pragma unroll
        for (int nt = 0; nt < 4; nt++) {
            size_t co = colBase + wnB + nt * 8 + cq * 2;
            if (r0 < M) {
                float2 v = make_float2(acc[mt][nt][0], acc[mt][nt][1]);
                *(float2*)&Out[(size_t)r0 * NFUSED + co] = v;
            }
            if (r0 + 8 < M) {
                float2 v = make_float2(acc[mt][nt][2], acc[mt][nt][3]);
                *(float2*)&Out[(size_t)(r0 + 8) * NFUSED + co] = v;
            }
        }
    }
}

// ---------------------------------------------------------------------------
// Main gate update, one step (fused N layout; writes tf32-rounded h)
// ---------------------------------------------------------------------------
__global__ void gate_step(int t, const float* __restrict__ bfi,
                          const float* __restrict__ bc, const float* __restrict__ bo) {
    int lin = blockIdx.x * 256 + threadIdx.x;
    if (lin >= MSTEP * MEM_SZ) return;
    int n = lin & (MEM_SZ - 1);
    int m = lin >> 9;
    int b = m / HW, hw = m % HW;
    size_t bigOff = ((size_t)t * MSTEP + m) * NFUSED;
    size_t hOff   = (size_t)m * NFUSED;
    float pfi = g_preM[bigOff + n]        + g_hpre[hOff + n]        + bfi[n];
    float pc  = g_preM[bigOff + 512 + n]  + g_hpre[hOff + 512 + n]  + bc[n];
    float po  = g_preM[bigOff + 1024 + n] + g_hpre[hOff + 1024 + n] + bo[n];
    float fi = sigmoidf_(pfi);
    float o  = sigmoidf_(po);
    float cn = fi * g_cstate[lin] + (1.0f - fi) * tanhf(pc);
    g_cstate[lin] = cn;
    float h = o * tanhf(cn);
    g_hpad[(size_t)(b * MEM_SZ + n) * PADHW + (hw / 7 + 1) * 9 + (hw % 7 + 1)] = rna_tf32(h);
}

// ---------------------------------------------------------------------------
// Final: feats = mean_hw(h); logits = feats @ W_fc^T + b_fc
// ---------------------------------------------------------------------------
__global__ void final_kernel(const float* __restrict__ W_fc, const float* __restrict__ b_fc,
                             float* __restrict__ logitsOut, float* __restrict__ featsOut) {
    int b = blockIdx.x, n = threadIdx.x;
    const float* hp = &g_hpad[(size_t)(b * MEM_SZ + n) * PADHW];
    float s = 0.f;
    #pragma unroll
    for (int hh = 1; hh <= 7; hh++)
        #pragma unroll
        for (int ww = 1; ww <= 7; ww++) s += hp[hh * 9 + ww];
    float f = s * (1.0f / 49.0f);
    __shared__ float fs[MEM_SZ];
    fs[n] = f;
    if (featsOut) featsOut[b * MEM_SZ + n] = f;
    __syncthreads();
    if (n < N_CLS && logitsOut) {
        float acc = b_fc[n];
        for (int k = 0; k < MEM_SZ; k++) acc += fs[k] * W_fc[n * MEM_SZ + k];
        logitsOut[b * N_CLS + n] = acc;
    }
}

// ---------------------------------------------------------------------------
// Host launcher
// ---------------------------------------------------------------------------
extern "C" void kernel_launch(void* const* d_in, const int* in_sizes, int n_in,
                              void* d_out, int out_size) {
    const float* x     = (const float*)d_in[0];
    const float* W_fi  = (const float*)d_in[1];
    const float* b_fi  = (const float*)d_in[2];
    const float* W_c   = (const float*)d_in[3];
    const float* b_c   = (const float*)d_in[4];
    const float* W_o   = (const float*)d_in[5];
    const float* b_o   = (const float*)d_in[6];
    const float* Ws_fi = (const float*)d_in[7];
    const float* bs_fi = (const float*)d_in[8];
    const float* Ws_c  = (const float*)d_in[9];
    const float* bs_c  = (const float*)d_in[10];
    const float* Ws_o  = (const float*)d_in[11];
    const float* bs_o  = (const float*)d_in[12];
    const float* W_cam = (const float*)d_in[13];
    const float* W_fc  = (const float*)d_in[14];
    const float* b_fc  = (const float*)d_in[15];

    float* xpad; cudaGetSymbolAddress((void**)&xpad, g_xpad);
    float* hpad; cudaGetSymbolAddress((void**)&hpad, g_hpad);
    float* wr;   cudaGetSymbolAddress((void**)&wr,   g_wr);
    float* pm;   cudaGetSymbolAddress((void**)&pm,   g_preM);
    float* hp;   cudaGetSymbolAddress((void**)&hp,   g_hpre);

    const int SMEM_BYTES = PIPE * STG_ * 4;   // 105984
    cudaFuncSetAttribute(conv_gemm_tc, cudaFuncAttributeMaxDynamicSharedMemorySize, SMEM_BYTES);

    float* outF = (float*)d_out;
    float* lp = nullptr; float* fp = nullptr;
    if (out_size >= B_SZ * N_CLS + B_SZ * MEM_SZ) { lp = outF; fp = outF + B_SZ * N_CLS; }
    else if (out_size == B_SZ * MEM_SZ)           { fp = outF; }
    else                                          { lp = outF; }

    // 1. reset recurrent state
    zero_states<<<(B_SZ * MEM_SZ * PADHW + 255) / 256, 256>>>();
    // 2. pad + tf32-round input; round weights
    pad_x<<<(TB * C_IN * PADHW + 255) / 256, 256>>>(x);
    round_weights<<<(MEM_SZ * NSTRIDE + 255) / 256, 256>>>(W_fi, W_c, W_o);
    // 3. attention-gate x contributions (all t)
    preS_kernel<<<MBIG, 256>>>(Ws_fi, Ws_c, Ws_o);
    // 4. CAM pipeline (all t)
    pooled_kernel<<<(TB * C_IN + 255) / 256, 256>>>(x);
    cam_logits_kernel<<<(TB * C_CAM + 3) / 4, 128>>>(W_cam);
    argmax_kernel<<<TB, 256>>>();
    cam_kernel<<<(TB * HW + 7) / 8, 256>>>(x, W_cam);
    cam_softmax_kernel<<<TB, 64>>>();
    // 5. sequential attention recurrence (cheap)
    for (int t = 0; t < T_STEPS; t++)
        att_step<<<B_SZ, 64>>>(t, Ws_fi, Ws_c, Ws_o, bs_fi, bs_c, bs_o);
    // 6. apply attention scaling (re-rounds to tf32)
    scale_x<<<(TB * C_IN * HW + 255) / 256, 256>>>();
    // 7. giant parallel GEMM: x_att conv contributions, all t, 3 gates fused
    {
        dim3 grid(12, (MBIG + 127) / 128);   // n-blocks fast -> L2 reuse
        conv_gemm_tc<<<grid, 256, SMEM_BYTES>>>(xpad, C_IN, MBIG, KX / 32, wr, 0, pm);
    }
    // 8. sequential main recurrence: h-part GEMM + gates per step
    for (int t = 0; t < T_STEPS; t++) {
        dim3 grid(12, (MSTEP + 127) / 128);
        conv_gemm_tc<<<grid, 256, SMEM_BYTES>>>(hpad, MEM_SZ, MSTEP, KH / 32, wr, KX, hp);
        gate_step<<<(MSTEP * MEM_SZ + 255) / 256, 256>>>(t, b_fi, b_c, b_o);
    }
    // 9. final pooling + FC head
    final_kernel<<<B_SZ, MEM_SZ>>>(W_fc, b_fc, lp, fp);
}

// round 6
// speedup vs baseline: 10.1340x; 2.5492x over previous
#include <cuda_runtime.h>
#include <math.h>
#include <stdint.h>

// ---------------------------------------------------------------------------
// Problem dims
// ---------------------------------------------------------------------------
#define T_STEPS 16
#define B_SZ    32
#define C_IN    2048
#define MEM_SZ  512
#define N_CLS   8
#define C_CAM   1000
#define HW      49
#define PADHW   81
#define KX      (C_IN*9)          // 18432
#define KH      (MEM_SZ*9)        // 4608
#define WROW    ((C_IN+MEM_SZ)*9) // 23040 original main-weight row stride
#define MBIG    (T_STEPS*B_SZ*HW) // 25088
#define MSTEP   (B_SZ*HW)         // 1568
#define TB      (T_STEPS*B_SZ)    // 512
#define NFUSED  (3*MEM_SZ)        // 1536
#define XROW    (PADHW*C_IN)      // 165888 floats per tb in xT
#define HROW    (PADHW*MEM_SZ)    // 41472 floats per b in hT

// ---------------------------------------------------------------------------
// Static device scratch
// ---------------------------------------------------------------------------
__device__ float g_xT[(size_t)TB * XROW];          // channels-last padded tf32 x (~340MB)
__device__ float g_hT[B_SZ * HROW];                // channels-last padded tf32 h
__device__ float g_wx[(size_t)3 * MEM_SZ * KX];    // tap-major tf32 x-part weights (113MB)
__device__ float g_wh[(size_t)3 * MEM_SZ * KH];    // tap-major tf32 h-part weights (28MB)
__device__ float g_wsx[3 * KX];                    // tap-major small att weights (x part)
__device__ float g_preS0[MBIG];
__device__ float g_preS1[MBIG];
__device__ float g_preS2[MBIG];
__device__ float g_attmap[MBIG];
__device__ float g_s[MBIG];
__device__ float g_pooled[TB * C_IN];
__device__ float g_logits[TB * C_CAM];
__device__ int   g_idx[TB];
__device__ float g_cam[TB * HW];
__device__ float g_preM[(size_t)MBIG * NFUSED];    // fused x-part pre-acts (154MB)
__device__ float g_hpre[(size_t)MSTEP * NFUSED];
__device__ float g_cstate[MSTEP * MEM_SZ];

__constant__ int c_border[32] = {
    0,1,2,3,4,5,6,7,8,              // row 0
    72,73,74,75,76,77,78,79,80,     // row 8
    9,17, 18,26, 27,35, 36,44, 45,53, 54,62, 63,71   // cols 0/8 rows 1..7
};

__device__ __forceinline__ float sigmoidf_(float x) { return 1.0f / (1.0f + expf(-x)); }
__device__ __forceinline__ float rna_tf32(float x) {
    unsigned u;
    asm("cvt.rna.tf32.f32 %0, %1;" : "=r"(u) : "f"(x));
    return __uint_as_float(u);
}

// ---------------------------------------------------------------------------
// Zero recurrent states
// ---------------------------------------------------------------------------
__global__ void zero_states() {
    int i = blockIdx.x * 256 + threadIdx.x;
    if (i < B_SZ * HROW)    g_hT[i] = 0.f;
    if (i < MSTEP * MEM_SZ) g_cstate[i] = 0.f;
}

// ---------------------------------------------------------------------------
// Zero border positions of xT (32 positions x TB x C_IN)
// ---------------------------------------------------------------------------
__global__ void border_zero() {
    size_t lin = (size_t)blockIdx.x * 256 + threadIdx.x;
    if (lin >= (size_t)TB * 32 * C_IN) return;
    int c  = lin & (C_IN - 1);
    int r  = (int)(lin >> 11);
    int bp = r & 31;
    int tb = r >> 5;
    g_xT[(size_t)tb * XROW + c_border[bp] * C_IN + c] = 0.f;
}

// ---------------------------------------------------------------------------
// Transpose NCHW x -> channels-last padded xT (tf32-rounded), tiled via smem
// grid (TB, C_IN/32), block 256
// ---------------------------------------------------------------------------
__global__ void pad_xT(const float* __restrict__ x) {
    __shared__ float tile[32][50];
    int tb = blockIdx.x, c0 = blockIdx.y * 32;
    int tid = threadIdx.x;
    for (int idx = tid; idx < 32 * HW; idx += 256) {
        int r = idx / HW, q = idx - HW * r;
        tile[r][q] = rna_tf32(x[((size_t)tb * C_IN + c0 + r) * HW + q]);
    }
    __syncthreads();
    for (int idx = tid; idx < HW * 32; idx += 256) {
        int q = idx >> 5, cl = idx & 31;
        int p = (q / 7 + 1) * 9 + (q % 7) + 1;
        g_xT[(size_t)tb * XROW + (size_t)p * C_IN + c0 + cl] = tile[cl][q];
    }
}

// ---------------------------------------------------------------------------
// Weight reorders: (c,kh,kw) -> (tap, c), tf32-rounded
// ---------------------------------------------------------------------------
__global__ void reorder_wx(const float* __restrict__ W0, const float* __restrict__ W1,
                           const float* __restrict__ W2) {
    size_t lin = (size_t)blockIdx.x * 256 + threadIdx.x;
    if (lin >= (size_t)3 * MEM_SZ * C_IN) return;
    int c = lin & (C_IN - 1);
    int r = (int)(lin >> 11);
    int n = r & (MEM_SZ - 1);
    int gate = r >> 9;
    const float* W = (gate == 0) ? W0 : (gate == 1 ? W1 : W2);
    const float* src = W + (size_t)n * WROW + (size_t)c * 9;
    float* dst = g_wx + ((size_t)gate * MEM_SZ + n) * KX + c;
    #pragma unroll
    for (int tap = 0; tap < 9; tap++) dst[(size_t)tap * C_IN] = rna_tf32(src[tap]);
}

__global__ void reorder_wh(const float* __restrict__ W0, const float* __restrict__ W1,
                           const float* __restrict__ W2) {
    size_t lin = (size_t)blockIdx.x * 256 + threadIdx.x;
    if (lin >= (size_t)3 * MEM_SZ * MEM_SZ) return;
    int c = lin & (MEM_SZ - 1);
    int r = (int)(lin >> 9);
    int n = r & (MEM_SZ - 1);
    int gate = r >> 9;
    const float* W = (gate == 0) ? W0 : (gate == 1 ? W1 : W2);
    const float* src = W + (size_t)n * WROW + (size_t)(C_IN + c) * 9;
    float* dst = g_wh + ((size_t)gate * MEM_SZ + n) * KH + c;
    #pragma unroll
    for (int tap = 0; tap < 9; tap++) dst[(size_t)tap * MEM_SZ] = rna_tf32(src[tap]);
}

__global__ void reorder_ws(const float* __restrict__ Wsfi, const float* __restrict__ Wsc,
                           const float* __restrict__ Wso) {
    int lin = blockIdx.x * 256 + threadIdx.x;
    if (lin >= 3 * C_IN) return;
    int gate = lin >> 11, c = lin & (C_IN - 1);
    const float* W = (gate == 0) ? Wsfi : (gate == 1 ? Wsc : Wso);
    #pragma unroll
    for (int tap = 0; tap < 9; tap++)
        g_wsx[gate * KX + tap * C_IN + c] = W[c * 9 + tap];
}

// ---------------------------------------------------------------------------
// Attention-gate x contributions. One block per tb; warps own hw positions;
// per-tap weight chunks staged in smem; coalesced xT reads.
// ---------------------------------------------------------------------------
__global__ __launch_bounds__(256) void preS_kernel() {
    int tb = blockIdx.x;
    int tid = threadIdx.x;
    int wid = tid >> 5, lane = tid & 31;
    __shared__ float ws[3 * C_IN];   // 24KB

    float acc[7][3];
    #pragma unroll
    for (int j = 0; j < 7; j++) { acc[j][0] = 0.f; acc[j][1] = 0.f; acc[j][2] = 0.f; }

    const float* xb = g_xT + (size_t)tb * XROW;

    for (int tap = 0; tap < 9; tap++) {
        __syncthreads();
        for (int idx = tid; idx < 3 * C_IN; idx += 256) {
            int g = idx >> 11, c = idx & (C_IN - 1);
            ws[idx] = g_wsx[g * KX + tap * C_IN + c];
        }
        __syncthreads();
        int dr = tap / 3, dc = tap - 3 * dr;
        #pragma unroll
        for (int j = 0; j < 7; j++) {
            int hw = wid + 8 * j;
            if (hw >= HW) break;
            int hh = hw / 7, ww = hw - 7 * hh;
            const float* xr = xb + (size_t)((hh + dr) * 9 + ww + dc) * C_IN;
            float a0 = 0.f, a1 = 0.f, a2 = 0.f;
            for (int c = lane; c < C_IN; c += 32) {
                float v = xr[c];
                a0 += v * ws[c];
                a1 += v * ws[C_IN + c];
                a2 += v * ws[2 * C_IN + c];
            }
            acc[j][0] += a0; acc[j][1] += a1; acc[j][2] += a2;
        }
    }
    #pragma unroll
    for (int j = 0; j < 7; j++) {
        int hw = wid + 8 * j;
        if (hw >= HW) break;
        float a0 = acc[j][0], a1 = acc[j][1], a2 = acc[j][2];
        #pragma unroll
        for (int o = 16; o > 0; o >>= 1) {
            a0 += __shfl_down_sync(0xffffffffu, a0, o);
            a1 += __shfl_down_sync(0xffffffffu, a1, o);
            a2 += __shfl_down_sync(0xffffffffu, a2, o);
        }
        if (lane == 0) {
            int m = tb * HW + hw;
            g_preS0[m] = a0; g_preS1[m] = a1; g_preS2[m] = a2;
        }
    }
}

// ---------------------------------------------------------------------------
// CAM pipeline (raw NCHW x)
// ---------------------------------------------------------------------------
__global__ void pooled_kernel(const float* __restrict__ x) {
    int lin = blockIdx.x * 256 + threadIdx.x;
    if (lin >= TB * C_IN) return;
    const float* p = x + (size_t)lin * HW;
    float s = 0.f;
    #pragma unroll
    for (int i = 0; i < HW; i++) s += p[i];
    g_pooled[lin] = s * (1.0f / 49.0f);
}

__global__ void cam_logits_kernel(const float* __restrict__ W_cam) {
    int gw   = blockIdx.x * 4 + (threadIdx.x >> 5);
    int lane = threadIdx.x & 31;
    if (gw >= TB * C_CAM) return;
    int tb = gw / C_CAM, j = gw % C_CAM;
    const float* p  = &g_pooled[tb * C_IN];
    const float* wr = &W_cam[(size_t)j * C_IN];
    float acc = 0.f;
    for (int c = lane; c < C_IN; c += 32) acc += p[c] * wr[c];
    #pragma unroll
    for (int o = 16; o > 0; o >>= 1) acc += __shfl_down_sync(0xffffffffu, acc, o);
    if (lane == 0) g_logits[gw] = acc;
}

__global__ void argmax_kernel() {
    int tb = blockIdx.x, tid = threadIdx.x;
    float best = -INFINITY; int bi = 0;
    for (int j = tid; j < C_CAM; j += 256) {
        float v = g_logits[tb * C_CAM + j];
        if (v > best) { best = v; bi = j; }
    }
    __shared__ float sv[256]; __shared__ int si[256];
    sv[tid] = best; si[tid] = bi; __syncthreads();
    for (int s = 128; s > 0; s >>= 1) {
        if (tid < s) {
            float v2 = sv[tid + s]; int i2 = si[tid + s];
            if (v2 > sv[tid] || (v2 == sv[tid] && i2 < si[tid])) { sv[tid] = v2; si[tid] = i2; }
        }
        __syncthreads();
    }
    if (tid == 0) g_idx[tb] = si[0];
}

__global__ void cam_kernel(const float* __restrict__ x, const float* __restrict__ W_cam) {
    int gw   = blockIdx.x * 8 + (threadIdx.x >> 5);
    int lane = threadIdx.x & 31;
    if (gw >= TB * HW) return;
    int tb = gw / HW, hw = gw % HW;
    const float* wsel = &W_cam[(size_t)g_idx[tb] * C_IN];
    const float* xp   = x + (size_t)tb * C_IN * HW + hw;
    float acc = 0.f;
    for (int c = lane; c < C_IN; c += 32) acc += wsel[c] * xp[(size_t)c * HW];
    #pragma unroll
    for (int o = 16; o > 0; o >>= 1) acc += __shfl_down_sync(0xffffffffu, acc, o);
    if (lane == 0) g_cam[gw] = acc;
}

__global__ void cam_softmax_kernel() {
    int tb = blockIdx.x, tid = threadIdx.x; // 64 threads
    __shared__ float v[HW]; __shared__ float red[64];
    if (tid < HW) v[tid] = g_cam[tb * HW + tid];
    __syncthreads();
    float m = (tid < HW) ? v[tid] : -INFINITY;
    red[tid] = m; __syncthreads();
    for (int s = 32; s > 0; s >>= 1) { if (tid < s) red[tid] = fmaxf(red[tid], red[tid + s]); __syncthreads(); }
    float mx = red[0]; __syncthreads();
    float e = (tid < HW) ? expf(v[tid] - mx) : 0.f;
    red[tid] = e; __syncthreads();
    for (int s = 32; s > 0; s >>= 1) { if (tid < s) red[tid] += red[tid + s]; __syncthreads(); }
    if (tid < HW) g_attmap[tb * HW + tid] = e / red[0];
}

// ---------------------------------------------------------------------------
// Fused attention recurrence: all 16 steps in one kernel, state in smem
// ---------------------------------------------------------------------------
__global__ void att_fused(const float* __restrict__ Wfi, const float* __restrict__ Wc,
                          const float* __restrict__ Wo,
                          const float* __restrict__ bfi, const float* __restrict__ bc,
                          const float* __restrict__ bo) {
    int b = blockIdx.x, tid = threadIdx.x; // 64 threads
    __shared__ float ap[HW], av[HW], csh[HW], red[64];
    if (tid < HW) { ap[tid] = 0.f; csh[tid] = 0.f; }
    __syncthreads();
    for (int t = 0; t < T_STEPS; t++) {
        if (tid < HW) {
            int h = tid / 7, w = tid % 7;
            float efi = 0.f, ec = 0.f, eo = 0.f;
            #pragma unroll
            for (int kh = 0; kh < 3; kh++)
                #pragma unroll
                for (int kw = 0; kw < 3; kw++) {
                    int hh = h + kh - 1, ww = w + kw - 1;
                    if (hh >= 0 && hh < 7 && ww >= 0 && ww < 7) {
                        float aval = ap[hh * 7 + ww];
                        int off = KX + kh * 3 + kw;
                        efi += aval * Wfi[off];
                        ec  += aval * Wc[off];
                        eo  += aval * Wo[off];
                    }
                }
            int base = (t * B_SZ + b) * HW + tid;
            float fi = sigmoidf_(g_preS0[base] + efi + bfi[0]);
            float o  = sigmoidf_(g_preS2[base] + eo + bo[0]);
            float cc = tanhf(g_preS1[base] + ec + bc[0]);
            float cs = fi * csh[tid] + (1.0f - fi) * cc;
            csh[tid] = cs;
            av[tid] = o * tanhf(cs) * g_attmap[base];
        }
        __syncthreads();
        float m = (tid < HW) ? av[tid] : -INFINITY;
        red[tid] = m; __syncthreads();
        for (int s = 32; s > 0; s >>= 1) { if (tid < s) red[tid] = fmaxf(red[tid], red[tid + s]); __syncthreads(); }
        float mx = red[0]; __syncthreads();
        float e = (tid < HW) ? expf(av[tid] - mx) : 0.f;
        red[tid] = e; __syncthreads();
        for (int s = 32; s > 0; s >>= 1) { if (tid < s) red[tid] += red[tid + s]; __syncthreads(); }
        if (tid < HW) {
            g_s[(t * B_SZ + b) * HW + tid] = e / red[0];
            ap[tid] = av[tid];
        }
        __syncthreads();
    }
}

// ---------------------------------------------------------------------------
// x_att: scale xT rows by softmax(a), re-round to tf32. Coalesced over c.
// ---------------------------------------------------------------------------
__global__ void scale_x() {
    size_t lin = (size_t)blockIdx.x * 256 + threadIdx.x;
    if (lin >= (size_t)TB * HW * C_IN) return;
    int c  = lin & (C_IN - 1);
    int rc = (int)(lin >> 11);        // tb*49 + hw
    int tb = rc / HW, hw = rc - HW * tb;
    float sc = g_s[rc];
    int p = (hw / 7 + 1) * 9 + (hw % 7) + 1;
    size_t a = (size_t)tb * XROW + (size_t)p * C_IN + c;
    g_xT[a] = rna_tf32(g_xT[a] * sc);
}

// ---------------------------------------------------------------------------
// TF32 tensor-core implicit GEMM, channels-last, tap-major K.
//   Out[m][gate*512+n] = sum_k A[m,k] * W[gate][n0in+n][k]
//   A[m, k=(tap,c)] = Apad[rowbase(m) + ((dr)*9+dc)*Crow + c]
// Block 128x128x32, 8 warps, mma.m16n8k8.tf32, 3-stage cp.async (16B, swizzled)
// ---------------------------------------------------------------------------
#define STG 8192   // floats per stage: 2 * 128 * 32
#define PIPE 3

__global__ __launch_bounds__(256, 2) void conv_gemm_tc(
    const float* __restrict__ Apad, int Crow, int cshift, int M, int KT, int Kfull,
    const float* __restrict__ Wbase, float* __restrict__ Out)
{
    extern __shared__ float sm[];
    const int tid  = threadIdx.x;
    const int m0   = blockIdx.y * 128;
    const int gate = blockIdx.x >> 2;
    const int n0in = (blockIdx.x & 3) * 128;
    const float* Wg = Wbase + ((size_t)gate * MEM_SZ + n0in) * Kfull;

    // ---- load geometry: 4 float4 per thread per operand ----
    const int rlo = tid >> 3;            // 0..31, row = rlo + 32*i
    const int kq  = (tid & 7) * 4;       // k offset within 32-chunk
    const int swz = (((kq >> 2) ^ (rlo & 7)) << 2);  // same for all i (32i keeps &7)

    size_t rowoff[4]; int sz[4];
    #pragma unroll
    for (int i = 0; i < 4; i++) {
        int m = m0 + rlo + 32 * i;
        if (m < M) {
            int tb = m / HW, hw = m - HW * tb;
            rowoff[i] = (size_t)tb * PADHW * Crow + (size_t)((hw / 7) * 9 + hw % 7) * Crow;
            sz[i] = 16;
        } else { rowoff[i] = 0; sz[i] = 0; }
    }

    // ---- warp/frag geometry ----
    const int lane = tid & 31;
    const int wid  = tid >> 5;
    const int g    = lane >> 2;
    const int cq   = lane & 3;
    const int wmB  = (wid & 1) * 64;
    const int wnB  = (wid >> 1) * 32;

    float acc[4][4][4];
    #pragma unroll
    for (int a = 0; a < 4; a++)
        #pragma unroll
        for (int b = 0; b < 4; b++)
            #pragma unroll
            for (int c = 0; c < 4; c++) acc[a][b][c] = 0.f;

    auto issue = [&](int s, int kt) {
        float* As_ = sm + s * STG;
        float* Bs_ = As_ + 128 * 32;
        uint32_t aB = (uint32_t)__cvta_generic_to_shared(As_);
        uint32_t bB = (uint32_t)__cvta_generic_to_shared(Bs_);
        int k0  = kt * 32;
        int tap = k0 >> cshift;
        int c0  = k0 & (Crow - 1);
        int dr  = tap / 3, dc = tap - 3 * dr;
        int poff = (dr * 9 + dc) * Crow + c0 + kq;
        #pragma unroll
        for (int i = 0; i < 4; i++) {
            const float* src = Apad + rowoff[i] + poff;
            uint32_t dst = aB + (uint32_t)((rlo + 32 * i) * 32 + swz) * 4u;
            asm volatile("cp.async.cg.shared.global [%0], [%1], 16, %2;\n"
                         :: "r"(dst), "l"(src), "r"(sz[i]));
        }
        #pragma unroll
        for (int i = 0; i < 4; i++) {
            const float* src = Wg + (size_t)(rlo + 32 * i) * Kfull + k0 + kq;
            uint32_t dst = bB + (uint32_t)((rlo + 32 * i) * 32 + swz) * 4u;
            asm volatile("cp.async.cg.shared.global [%0], [%1], 16;\n"
                         :: "r"(dst), "l"(src));
        }
        asm volatile("cp.async.commit_group;\n");
    };

    #pragma unroll
    for (int s = 0; s < PIPE - 1; s++)
        if (s < KT) issue(s, s);

    for (int kt = 0; kt < KT; kt++) {
        if (kt + 1 < KT) asm volatile("cp.async.wait_group 1;\n");
        else             asm volatile("cp.async.wait_group 0;\n");
        __syncthreads();
        if (kt + PIPE - 1 < KT) issue((kt + PIPE - 1) % PIPE, kt + PIPE - 1);

        const float* As_ = sm + (kt % PIPE) * STG;
        const float* Bs_ = As_ + 128 * 32;

        #pragma unroll
        for (int ks = 0; ks < 4; ks++) {
            int g0 = ((2 * ks) ^ g) << 2;   // swizzled k-group offsets (m&7 == g)
            int g1 = g0 ^ 4;
            unsigned af[4][4], bf[4][2];
            #pragma unroll
            for (int mt = 0; mt < 4; mt++) {
                const float* ap = As_ + (wmB + mt * 16 + g) * 32 + cq;
                af[mt][0] = __float_as_uint(ap[g0]);
                af[mt][1] = __float_as_uint(ap[8 * 32 + g0]);
                af[mt][2] = __float_as_uint(ap[g1]);
                af[mt][3] = __float_as_uint(ap[8 * 32 + g1]);
            }
            #pragma unroll
            for (int nt = 0; nt < 4; nt++) {
                const float* bp = Bs_ + (wnB + nt * 8 + g) * 32 + cq;
                bf[nt][0] = __float_as_uint(bp[g0]);
                bf[nt][1] = __float_as_uint(bp[g1]);
            }
            #pragma unroll
            for (int mt = 0; mt < 4; mt++)
                #pragma unroll
                for (int nt = 0; nt < 4; nt++) {
                    asm volatile(
                        "mma.sync.aligned.m16n8k8.row.col.f32.tf32.tf32.f32 "
                        "{%0,%1,%2,%3}, {%4,%5,%6,%7}, {%8,%9}, {%0,%1,%2,%3};\n"
                        : "+f"(acc[mt][nt][0]), "+f"(acc[mt][nt][1]),
                          "+f"(acc[mt][nt][2]), "+f"(acc[mt][nt][3])
                        : "r"(af[mt][0]), "r"(af[mt][1]), "r"(af[mt][2]), "r"(af[mt][3]),
                          "r"(bf[nt][0]), "r"(bf[nt][1]));
                }
        }
        __syncthreads();
    }

    const size_t colBase = (size_t)(gate * MEM_SZ + n0in);
    #pragma unroll
    for (int mt = 0; mt < 4; mt++) {
        int r0 = m0 + wmB + mt * 16 + g;
        #pragma unroll
        for (int nt = 0; nt < 4; nt++) {
            size_t co = colBase + wnB + nt * 8 + cq * 2;
            if (r0 < M) {
                float2 v = make_float2(acc[mt][nt][0], acc[mt][nt][1]);
                *(float2*)&Out[(size_t)r0 * NFUSED + co] = v;
            }
            if (r0 + 8 < M) {
                float2 v = make_float2(acc[mt][nt][2], acc[mt][nt][3]);
                *(float2*)&Out[(size_t)(r0 + 8) * NFUSED + co] = v;
            }
        }
    }
}

// ---------------------------------------------------------------------------
// Main gate update, one step; writes channels-last tf32 h (coalesced)
// ---------------------------------------------------------------------------
__global__ void gate_step(int t, const float* __restrict__ bfi,
                          const float* __restrict__ bc, const float* __restrict__ bo) {
    int lin = blockIdx.x * 256 + threadIdx.x;
    if (lin >= MSTEP * MEM_SZ) return;
    int n = lin & (MEM_SZ - 1);
    int m = lin >> 9;
    int b = m / HW, hw = m - HW * b;
    size_t bigOff = ((size_t)t * MSTEP + m) * NFUSED;
    size_t hOff   = (size_t)m * NFUSED;
    float pfi = g_preM[bigOff + n]        + g_hpre[hOff + n]        + bfi[n];
    float pc  = g_preM[bigOff + 512 + n]  + g_hpre[hOff + 512 + n]  + bc[n];
    float po  = g_preM[bigOff + 1024 + n] + g_hpre[hOff + 1024 + n] + bo[n];
    float fi = sigmoidf_(pfi);
    float o  = sigmoidf_(po);
    float cn = fi * g_cstate[lin] + (1.0f - fi) * tanhf(pc);
    g_cstate[lin] = cn;
    float h = o * tanhf(cn);
    int p = (hw / 7 + 1) * 9 + (hw % 7) + 1;
    g_hT[(size_t)b * HROW + (size_t)p * MEM_SZ + n] = rna_tf32(h);
}

// ---------------------------------------------------------------------------
// Final: feats = mean_hw(h); logits = feats @ W_fc^T + b_fc
// ---------------------------------------------------------------------------
__global__ void final_kernel(const float* __restrict__ W_fc, const float* __restrict__ b_fc,
                             float* __restrict__ logitsOut, float* __restrict__ featsOut) {
    int b = blockIdx.x, n = threadIdx.x;
    const float* hb = &g_hT[(size_t)b * HROW];
    float s = 0.f;
    #pragma unroll
    for (int hh = 1; hh <= 7; hh++)
        #pragma unroll
        for (int ww = 1; ww <= 7; ww++) s += hb[(size_t)(hh * 9 + ww) * MEM_SZ + n];
    float f = s * (1.0f / 49.0f);
    __shared__ float fs[MEM_SZ];
    fs[n] = f;
    if (featsOut) featsOut[b * MEM_SZ + n] = f;
    __syncthreads();
    if (n < N_CLS && logitsOut) {
        float acc = b_fc[n];
        for (int k = 0; k < MEM_SZ; k++) acc += fs[k] * W_fc[n * MEM_SZ + k];
        logitsOut[b * N_CLS + n] = acc;
    }
}

// ---------------------------------------------------------------------------
// Host launcher
// ---------------------------------------------------------------------------
extern "C" void kernel_launch(void* const* d_in, const int* in_sizes, int n_in,
                              void* d_out, int out_size) {
    const float* x     = (const float*)d_in[0];
    const float* W_fi  = (const float*)d_in[1];
    const float* b_fi  = (const float*)d_in[2];
    const float* W_c   = (const float*)d_in[3];
    const float* b_c   = (const float*)d_in[4];
    const float* W_o   = (const float*)d_in[5];
    const float* b_o   = (const float*)d_in[6];
    const float* Ws_fi = (const float*)d_in[7];
    const float* bs_fi = (const float*)d_in[8];
    const float* Ws_c  = (const float*)d_in[9];
    const float* bs_c  = (const float*)d_in[10];
    const float* Ws_o  = (const float*)d_in[11];
    const float* bs_o  = (const float*)d_in[12];
    const float* W_cam = (const float*)d_in[13];
    const float* W_fc  = (const float*)d_in[14];
    const float* b_fc  = (const float*)d_in[15];

    float* xT; cudaGetSymbolAddress((void**)&xT, g_xT);
    float* hT; cudaGetSymbolAddress((void**)&hT, g_hT);
    float* wx; cudaGetSymbolAddress((void**)&wx, g_wx);
    float* wh; cudaGetSymbolAddress((void**)&wh, g_wh);
    float* pm; cudaGetSymbolAddress((void**)&pm, g_preM);
    float* hp; cudaGetSymbolAddress((void**)&hp, g_hpre);

    const int SMEM_BYTES = PIPE * STG * 4;   // 98304
    cudaFuncSetAttribute(conv_gemm_tc, cudaFuncAttributeMaxDynamicSharedMemorySize, SMEM_BYTES);

    float* outF = (float*)d_out;
    float* lp = nullptr; float* fp = nullptr;
    if (out_size >= B_SZ * N_CLS + B_SZ * MEM_SZ) { lp = outF; fp = outF + B_SZ * N_CLS; }
    else if (out_size == B_SZ * MEM_SZ)           { fp = outF; }
    else                                          { lp = outF; }

    // 1. reset recurrent state; zero xT borders
    zero_states<<<(B_SZ * HROW + 255) / 256, 256>>>();
    border_zero<<<(int)(((size_t)TB * 32 * C_IN + 255) / 256), 256>>>();
    // 2. transpose + pad + tf32-round input; reorder weights
    {
        dim3 grid(TB, C_IN / 32);
        pad_xT<<<grid, 256>>>(x);
    }
    reorder_wx<<<(int)(((size_t)3 * MEM_SZ * C_IN + 255) / 256), 256>>>(W_fi, W_c, W_o);
    reorder_wh<<<(int)(((size_t)3 * MEM_SZ * MEM_SZ + 255) / 256), 256>>>(W_fi, W_c, W_o);
    reorder_ws<<<(3 * C_IN + 255) / 256, 256>>>(Ws_fi, Ws_c, Ws_o);
    // 3. attention-gate x contributions
    preS_kernel<<<TB, 256>>>();
    // 4. CAM pipeline
    pooled_kernel<<<(TB * C_IN + 255) / 256, 256>>>(x);
    cam_logits_kernel<<<(TB * C_CAM + 3) / 4, 128>>>(W_cam);
    argmax_kernel<<<TB, 256>>>();
    cam_kernel<<<(TB * HW + 7) / 8, 256>>>(x, W_cam);
    cam_softmax_kernel<<<TB, 64>>>();
    // 5. fused attention recurrence (16 steps in one kernel)
    att_fused<<<B_SZ, 64>>>(Ws_fi, Ws_c, Ws_o, bs_fi, bs_c, bs_o);
    // 6. attention scaling
    scale_x<<<(int)(((size_t)TB * HW * C_IN + 255) / 256), 256>>>();
    // 7. giant parallel GEMM (x part, all t, 3 gates)
    {
        dim3 grid(12, MBIG / 128);
        conv_gemm_tc<<<grid, 256, SMEM_BYTES>>>(xT, C_IN, 11, MBIG, KX / 32, KX, wx, pm);
    }
    // 8. sequential main recurrence
    for (int t = 0; t < T_STEPS; t++) {
        dim3 grid(12, (MSTEP + 127) / 128);
        conv_gemm_tc<<<grid, 256, SMEM_BYTES>>>(hT, MEM_SZ, 9, MSTEP, KH / 32, KH, wh, hp);
        gate_step<<<(MSTEP * MEM_SZ + 255) / 256, 256>>>(t, b_fi, b_c, b_o);
    }
    // 9. final pooling + FC head
    final_kernel<<<B_SZ, MEM_SZ>>>(W_fc, b_fc, lp, fp);
}

// round 8
// speedup vs baseline: 18.6183x; 1.8372x over previous
#include <cuda_runtime.h>
#include <cuda_fp16.h>
#include <math.h>
#include <stdint.h>

// ---------------------------------------------------------------------------
// Problem dims
// ---------------------------------------------------------------------------
#define T_STEPS 16
#define B_SZ    32
#define C_IN    2048
#define MEM_SZ  512
#define N_CLS   8
#define C_CAM   1000
#define HW      49
#define PADHW   81
#define KX      (C_IN*9)          // 18432
#define KH      (MEM_SZ*9)        // 4608
#define WROW    ((C_IN+MEM_SZ)*9) // 23040 original main-weight row stride
#define MBIG    (T_STEPS*B_SZ*HW) // 25088
#define MSTEP   (B_SZ*HW)         // 1568
#define TB      (T_STEPS*B_SZ)    // 512
#define NFUSED  (3*MEM_SZ)        // 1536
#define XROW    (PADHW*C_IN)      // halves per tb in xT
#define HROW    (PADHW*MEM_SZ)    // halves per b in hT

// ---------------------------------------------------------------------------
// Static device scratch (fp16 GEMM operands, fp32 elsewhere)
// ---------------------------------------------------------------------------
__device__ __half g_xT[(size_t)TB * XROW];
__device__ __half g_hT[B_SZ * HROW];
__device__ __half g_wx[(size_t)3 * MEM_SZ * KX];
__device__ __half g_wh[(size_t)3 * MEM_SZ * KH];
__device__ float  g_wsx[3 * KX];
__device__ float  g_preS0[MBIG];
__device__ float  g_preS1[MBIG];
__device__ float  g_preS2[MBIG];
__device__ float  g_attmap[MBIG];
__device__ float  g_s[MBIG];
__device__ float  g_pooled[TB * C_IN];
__device__ float  g_logits[TB * C_CAM];
__device__ int    g_idx[TB];
__device__ float  g_cam[TB * HW];
__device__ float  g_preM[(size_t)MBIG * NFUSED];
__device__ float  g_hpre[(size_t)MSTEP * NFUSED];
__device__ float  g_cstate[MSTEP * MEM_SZ];

__constant__ int c_border[32] = {
    0,1,2,3,4,5,6,7,8,
    72,73,74,75,76,77,78,79,80,
    9,17, 18,26, 27,35, 36,44, 45,53, 54,62, 63,71
};

__device__ __forceinline__ float sigmoidf_(float x) { return 1.0f / (1.0f + expf(-x)); }

// ---------------------------------------------------------------------------
// Zero recurrent states
// ---------------------------------------------------------------------------
__global__ void zero_states() {
    int i = blockIdx.x * 256 + threadIdx.x;
    if (i < B_SZ * HROW)    g_hT[i] = __float2half_rn(0.f);
    if (i < MSTEP * MEM_SZ) g_cstate[i] = 0.f;
}

// ---------------------------------------------------------------------------
// Zero border positions of xT
// ---------------------------------------------------------------------------
__global__ void border_zero() {
    size_t lin = (size_t)blockIdx.x * 256 + threadIdx.x;
    if (lin >= (size_t)TB * 32 * C_IN) return;
    int c  = lin & (C_IN - 1);
    int r  = (int)(lin >> 11);
    int bp = r & 31;
    int tb = r >> 5;
    g_xT[(size_t)tb * XROW + c_border[bp] * C_IN + c] = __float2half_rn(0.f);
}

// ---------------------------------------------------------------------------
// Transpose NCHW x -> channels-last padded fp16 xT
// ---------------------------------------------------------------------------
__global__ void pad_xT(const float* __restrict__ x) {
    __shared__ float tile[32][50];
    int tb = blockIdx.x, c0 = blockIdx.y * 32;
    int tid = threadIdx.x;
    for (int idx = tid; idx < 32 * HW; idx += 256) {
        int r = idx / HW, q = idx - HW * r;
        tile[r][q] = x[((size_t)tb * C_IN + c0 + r) * HW + q];
    }
    __syncthreads();
    for (int idx = tid; idx < HW * 32; idx += 256) {
        int q = idx >> 5, cl = idx & 31;
        int p = (q / 7 + 1) * 9 + (q % 7) + 1;
        g_xT[(size_t)tb * XROW + (size_t)p * C_IN + c0 + cl] = __float2half_rn(tile[cl][q]);
    }
}

// ---------------------------------------------------------------------------
// Weight reorders: (c,kh,kw) -> (tap, c), fp16
// ---------------------------------------------------------------------------
__global__ void reorder_wx(const float* __restrict__ W0, const float* __restrict__ W1,
                           const float* __restrict__ W2) {
    size_t lin = (size_t)blockIdx.x * 256 + threadIdx.x;
    if (lin >= (size_t)3 * MEM_SZ * C_IN) return;
    int c = lin & (C_IN - 1);
    int r = (int)(lin >> 11);
    int n = r & (MEM_SZ - 1);
    int gate = r >> 9;
    const float* W = (gate == 0) ? W0 : (gate == 1 ? W1 : W2);
    const float* src = W + (size_t)n * WROW + (size_t)c * 9;
    __half* dst = g_wx + ((size_t)gate * MEM_SZ + n) * KX + c;
    #pragma unroll
    for (int tap = 0; tap < 9; tap++) dst[(size_t)tap * C_IN] = __float2half_rn(src[tap]);
}

__global__ void reorder_wh(const float* __restrict__ W0, const float* __restrict__ W1,
                           const float* __restrict__ W2) {
    size_t lin = (size_t)blockIdx.x * 256 + threadIdx.x;
    if (lin >= (size_t)3 * MEM_SZ * MEM_SZ) return;
    int c = lin & (MEM_SZ - 1);
    int r = (int)(lin >> 9);
    int n = r & (MEM_SZ - 1);
    int gate = r >> 9;
    const float* W = (gate == 0) ? W0 : (gate == 1 ? W1 : W2);
    const float* src = W + (size_t)n * WROW + (size_t)(C_IN + c) * 9;
    __half* dst = g_wh + ((size_t)gate * MEM_SZ + n) * KH + c;
    #pragma unroll
    for (int tap = 0; tap < 9; tap++) dst[(size_t)tap * MEM_SZ] = __float2half_rn(src[tap]);
}

__global__ void reorder_ws(const float* __restrict__ Wsfi, const float* __restrict__ Wsc,
                           const float* __restrict__ Wso) {
    int lin = blockIdx.x * 256 + threadIdx.x;
    if (lin >= 3 * C_IN) return;
    int gate = lin >> 11, c = lin & (C_IN - 1);
    const float* W = (gate == 0) ? Wsfi : (gate == 1 ? Wsc : Wso);
    #pragma unroll
    for (int tap = 0; tap < 9; tap++)
        g_wsx[gate * KX + tap * C_IN + c] = W[c * 9 + tap];
}

// ---------------------------------------------------------------------------
// Attention-gate x contributions (fp32 math, fp16 x reads)
// ---------------------------------------------------------------------------
__global__ __launch_bounds__(256) void preS_kernel() {
    int tb = blockIdx.x;
    int tid = threadIdx.x;
    int wid = tid >> 5, lane = tid & 31;
    __shared__ float ws[3 * C_IN];

    float acc[7][3];
    #pragma unroll
    for (int j = 0; j < 7; j++) { acc[j][0] = 0.f; acc[j][1] = 0.f; acc[j][2] = 0.f; }

    const __half* xb = g_xT + (size_t)tb * XROW;

    for (int tap = 0; tap < 9; tap++) {
        __syncthreads();
        for (int idx = tid; idx < 3 * C_IN; idx += 256) {
            int g = idx >> 11, c = idx & (C_IN - 1);
            ws[idx] = g_wsx[g * KX + tap * C_IN + c];
        }
        __syncthreads();
        int dr = tap / 3, dc = tap - 3 * dr;
        #pragma unroll
        for (int j = 0; j < 7; j++) {
            int hw = wid + 8 * j;
            if (hw >= HW) break;
            int hh = hw / 7, ww = hw - 7 * hh;
            const __half* xr = xb + (size_t)((hh + dr) * 9 + ww + dc) * C_IN;
            float a0 = 0.f, a1 = 0.f, a2 = 0.f;
            for (int c = lane; c < C_IN; c += 32) {
                float v = __half2float(xr[c]);
                a0 += v * ws[c];
                a1 += v * ws[C_IN + c];
                a2 += v * ws[2 * C_IN + c];
            }
            acc[j][0] += a0; acc[j][1] += a1; acc[j][2] += a2;
        }
    }
    #pragma unroll
    for (int j = 0; j < 7; j++) {
        int hw = wid + 8 * j;
        if (hw >= HW) break;
        float a0 = acc[j][0], a1 = acc[j][1], a2 = acc[j][2];
        #pragma unroll
        for (int o = 16; o > 0; o >>= 1) {
            a0 += __shfl_down_sync(0xffffffffu, a0, o);
            a1 += __shfl_down_sync(0xffffffffu, a1, o);
            a2 += __shfl_down_sync(0xffffffffu, a2, o);
        }
        if (lane == 0) {
            int m = tb * HW + hw;
            g_preS0[m] = a0; g_preS1[m] = a1; g_preS2[m] = a2;
        }
    }
}

// ---------------------------------------------------------------------------
// CAM pipeline (raw NCHW x)
// ---------------------------------------------------------------------------
__global__ void pooled_kernel(const float* __restrict__ x) {
    int lin = blockIdx.x * 256 + threadIdx.x;
    if (lin >= TB * C_IN) return;
    const float* p = x + (size_t)lin * HW;
    float s = 0.f;
    #pragma unroll
    for (int i = 0; i < HW; i++) s += p[i];
    g_pooled[lin] = s * (1.0f / 49.0f);
}

__global__ void cam_logits_kernel(const float* __restrict__ W_cam) {
    int gw   = blockIdx.x * 4 + (threadIdx.x >> 5);
    int lane = threadIdx.x & 31;
    if (gw >= TB * C_CAM) return;
    int tb = gw / C_CAM, j = gw % C_CAM;
    const float* p  = &g_pooled[tb * C_IN];
    const float* wr = &W_cam[(size_t)j * C_IN];
    float acc = 0.f;
    for (int c = lane; c < C_IN; c += 32) acc += p[c] * wr[c];
    #pragma unroll
    for (int o = 16; o > 0; o >>= 1) acc += __shfl_down_sync(0xffffffffu, acc, o);
    if (lane == 0) g_logits[gw] = acc;
}

__global__ void argmax_kernel() {
    int tb = blockIdx.x, tid = threadIdx.x;
    float best = -INFINITY; int bi = 0;
    for (int j = tid; j < C_CAM; j += 256) {
        float v = g_logits[tb * C_CAM + j];
        if (v > best) { best = v; bi = j; }
    }
    __shared__ float sv[256]; __shared__ int si[256];
    sv[tid] = best; si[tid] = bi; __syncthreads();
    for (int s = 128; s > 0; s >>= 1) {
        if (tid < s) {
            float v2 = sv[tid + s]; int i2 = si[tid + s];
            if (v2 > sv[tid] || (v2 == sv[tid] && i2 < si[tid])) { sv[tid] = v2; si[tid] = i2; }
        }
        __syncthreads();
    }
    if (tid == 0) g_idx[tb] = si[0];
}

__global__ void cam_kernel(const float* __restrict__ x, const float* __restrict__ W_cam) {
    int gw   = blockIdx.x * 8 + (threadIdx.x >> 5);
    int lane = threadIdx.x & 31;
    if (gw >= TB * HW) return;
    int tb = gw / HW, hw = gw % HW;
    const float* wsel = &W_cam[(size_t)g_idx[tb] * C_IN];
    const float* xp   = x + (size_t)tb * C_IN * HW + hw;
    float acc = 0.f;
    for (int c = lane; c < C_IN; c += 32) acc += wsel[c] * xp[(size_t)c * HW];
    #pragma unroll
    for (int o = 16; o > 0; o >>= 1) acc += __shfl_down_sync(0xffffffffu, acc, o);
    if (lane == 0) g_cam[gw] = acc;
}

__global__ void cam_softmax_kernel() {
    int tb = blockIdx.x, tid = threadIdx.x;
    __shared__ float v[HW]; __shared__ float red[64];
    if (tid < HW) v[tid] = g_cam[tb * HW + tid];
    __syncthreads();
    float m = (tid < HW) ? v[tid] : -INFINITY;
    red[tid] = m; __syncthreads();
    for (int s = 32; s > 0; s >>= 1) { if (tid < s) red[tid] = fmaxf(red[tid], red[tid + s]); __syncthreads(); }
    float mx = red[0]; __syncthreads();
    float e = (tid < HW) ? expf(v[tid] - mx) : 0.f;
    red[tid] = e; __syncthreads();
    for (int s = 32; s > 0; s >>= 1) { if (tid < s) red[tid] += red[tid + s]; __syncthreads(); }
    if (tid < HW) g_attmap[tb * HW + tid] = e / red[0];
}

// ---------------------------------------------------------------------------
// Fused attention recurrence
// ---------------------------------------------------------------------------
__global__ void att_fused(const float* __restrict__ Wfi, const float* __restrict__ Wc,
                          const float* __restrict__ Wo,
                          const float* __restrict__ bfi, const float* __restrict__ bc,
                          const float* __restrict__ bo) {
    int b = blockIdx.x, tid = threadIdx.x;
    __shared__ float ap[HW], av[HW], csh[HW], red[64];
    if (tid < HW) { ap[tid] = 0.f; csh[tid] = 0.f; }
    __syncthreads();
    for (int t = 0; t < T_STEPS; t++) {
        if (tid < HW) {
            int h = tid / 7, w = tid % 7;
            float efi = 0.f, ec = 0.f, eo = 0.f;
            #pragma unroll
            for (int kh = 0; kh < 3; kh++)
                #pragma unroll
                for (int kw = 0; kw < 3; kw++) {
                    int hh = h + kh - 1, ww = w + kw - 1;
                    if (hh >= 0 && hh < 7 && ww >= 0 && ww < 7) {
                        float aval = ap[hh * 7 + ww];
                        int off = KX + kh * 3 + kw;
                        efi += aval * Wfi[off];
                        ec  += aval * Wc[off];
                        eo  += aval * Wo[off];
                    }
                }
            int base = (t * B_SZ + b) * HW + tid;
            float fi = sigmoidf_(g_preS0[base] + efi + bfi[0]);
            float o  = sigmoidf_(g_preS2[base] + eo + bo[0]);
            float cc = tanhf(g_preS1[base] + ec + bc[0]);
            float cs = fi * csh[tid] + (1.0f - fi) * cc;
            csh[tid] = cs;
            av[tid] = o * tanhf(cs) * g_attmap[base];
        }
        __syncthreads();
        float m = (tid < HW) ? av[tid] : -INFINITY;
        red[tid] = m; __syncthreads();
        for (int s = 32; s > 0; s >>= 1) { if (tid < s) red[tid] = fmaxf(red[tid], red[tid + s]); __syncthreads(); }
        float mx = red[0]; __syncthreads();
        float e = (tid < HW) ? expf(av[tid] - mx) : 0.f;
        red[tid] = e; __syncthreads();
        for (int s = 32; s > 0; s >>= 1) { if (tid < s) red[tid] += red[tid + s]; __syncthreads(); }
        if (tid < HW) {
            g_s[(t * B_SZ + b) * HW + tid] = e / red[0];
            ap[tid] = av[tid];
        }
        __syncthreads();
    }
}

// ---------------------------------------------------------------------------
// x_att scaling (coalesced over c), fp16 in/out
// ---------------------------------------------------------------------------
__global__ void scale_x() {
    size_t lin = (size_t)blockIdx.x * 256 + threadIdx.x;
    if (lin >= (size_t)TB * HW * C_IN) return;
    int c  = lin & (C_IN - 1);
    int rc = (int)(lin >> 11);
    int tb = rc / HW, hw = rc - HW * tb;
    float sc = g_s[rc];
    int p = (hw / 7 + 1) * 9 + (hw % 7) + 1;
    size_t a = (size_t)tb * XROW + (size_t)p * C_IN + c;
    g_xT[a] = __float2half_rn(__half2float(g_xT[a]) * sc);
}

// ---------------------------------------------------------------------------
// FP16 tensor-core implicit GEMM (mma.sync.m16n8k16), channels-last, tap-major.
// Block 128(M) x 128(N) x 64(K), 8 warps (2x4), warp tile 64x32,
// 3-stage cp.async (16B, 128B-row XOR swizzle).
// grid.x = 12 (gate*4 + nb) -> L2-friendly waves.
// ---------------------------------------------------------------------------
#define STGB 32768           // bytes per stage: (128*64 + 128*64) halves
#define PIPE 3

__global__ __launch_bounds__(256, 2) void conv_gemm_fp16(
    const __half* __restrict__ Apad, int Crow, int cshift, int M, int KT, int Kfull,
    const __half* __restrict__ Wbase, float* __restrict__ Out)
{
    extern __shared__ char smc[];
    const int tid  = threadIdx.x;
    const int m0   = blockIdx.y * 128;
    const int gate = blockIdx.x >> 2;
    const int n0in = (blockIdx.x & 3) * 128;
    const __half* Wg = Wbase + ((size_t)gate * MEM_SZ + n0in) * Kfull;

    // ---- load geometry: 4 x 16B per operand per thread ----
    const int rlo = tid >> 3;            // 0..31, row = rlo + 32*i
    const int kq  = (tid & 7) * 8;       // half offset within 64-half row
    const int stChunk = ((tid & 7) ^ (rlo & 7)) << 4;  // swizzled 16B chunk byte off

    size_t rowoff[4]; int asz[4];
    #pragma unroll
    for (int i = 0; i < 4; i++) {
        int m = m0 + rlo + 32 * i;
        if (m < M) {
            int tb = m / HW, hw = m - HW * tb;
            rowoff[i] = ((size_t)tb * PADHW + (size_t)((hw / 7) * 9 + hw % 7)) * Crow;
            asz[i] = 16;
        } else { rowoff[i] = 0; asz[i] = 0; }
    }

    // ---- warp/frag geometry ----
    const int lane = tid & 31;
    const int wid  = tid >> 5;
    const int g    = lane >> 2;
    const int cq   = lane & 3;
    const int wmB  = (wid & 1) * 64;
    const int wnB  = (wid >> 1) * 32;

    float acc[4][4][4];
    #pragma unroll
    for (int a = 0; a < 4; a++)
        #pragma unroll
        for (int b = 0; b < 4; b++)
            #pragma unroll
            for (int c = 0; c < 4; c++) acc[a][b][c] = 0.f;

    auto issue = [&](int s, int kt) {
        char* As_ = smc + s * STGB;
        char* Bs_ = As_ + 16384;
        uint32_t aB = (uint32_t)__cvta_generic_to_shared(As_);
        uint32_t bB = (uint32_t)__cvta_generic_to_shared(Bs_);
        int k0  = kt * 64;
        int tap = k0 >> cshift;
        int c0  = k0 & (Crow - 1);
        int dr  = tap / 3, dc = tap - 3 * dr;
        size_t poff = (size_t)(dr * 9 + dc) * Crow + c0 + kq;
        #pragma unroll
        for (int i = 0; i < 4; i++) {
            const __half* src = Apad + rowoff[i] + poff;
            uint32_t dst = aB + (uint32_t)((rlo + 32 * i) * 128 + stChunk);
            asm volatile("cp.async.cg.shared.global [%0], [%1], 16, %2;\n"
                         :: "r"(dst), "l"(src), "r"(asz[i]));
        }
        #pragma unroll
        for (int i = 0; i < 4; i++) {
            int nl = rlo + 32 * i;
            const __half* src = Wg + (size_t)nl * Kfull + k0 + kq;
            uint32_t dst = bB + (uint32_t)(nl * 128 + stChunk);
            asm volatile("cp.async.cg.shared.global [%0], [%1], 16;\n"
                         :: "r"(dst), "l"(src));
        }
        asm volatile("cp.async.commit_group;\n");
    };

    #pragma unroll
    for (int s = 0; s < PIPE - 1; s++)
        if (s < KT) issue(s, s);

    for (int kt = 0; kt < KT; kt++) {
        if (kt + 1 < KT) asm volatile("cp.async.wait_group 1;\n" ::: "memory");
        else             asm volatile("cp.async.wait_group 0;\n" ::: "memory");
        __syncthreads();
        if (kt + PIPE - 1 < KT) issue((kt + PIPE - 1) % PIPE, kt + PIPE - 1);

        const char* As_ = smc + (kt % PIPE) * STGB;
        const char* Bs_ = As_ + 16384;

        #pragma unroll
        for (int ks = 0; ks < 4; ks++) {
            // swizzled chunk byte offsets for this k16-step (rows have row&7 == g)
            const int ch0 = (((2 * ks)     ^ g) << 4) + 4 * cq;
            const int ch1 = (((2 * ks + 1) ^ g) << 4) + 4 * cq;
            unsigned af[4][4], bf[4][2];
            #pragma unroll
            for (int mt = 0; mt < 4; mt++) {
                const char* r0p = As_ + (wmB + mt * 16 + g) * 128;
                const char* r1p = r0p + 8 * 128;
                af[mt][0] = *(const uint32_t*)(r0p + ch0);
                af[mt][1] = *(const uint32_t*)(r1p + ch0);
                af[mt][2] = *(const uint32_t*)(r0p + ch1);
                af[mt][3] = *(const uint32_t*)(r1p + ch1);
            }
            #pragma unroll
            for (int nt = 0; nt < 4; nt++) {
                const char* np = Bs_ + (wnB + nt * 8 + g) * 128;
                bf[nt][0] = *(const uint32_t*)(np + ch0);
                bf[nt][1] = *(const uint32_t*)(np + ch1);
            }
            #pragma unroll
            for (int mt = 0; mt < 4; mt++)
                #pragma unroll
                for (int nt = 0; nt < 4; nt++) {
                    asm volatile(
                        "mma.sync.aligned.m16n8k16.row.col.f32.f16.f16.f32 "
                        "{%0,%1,%2,%3}, {%4,%5,%6,%7}, {%8,%9}, {%0,%1,%2,%3};\n"
                        : "+f"(acc[mt][nt][0]), "+f"(acc[mt][nt][1]),
                          "+f"(acc[mt][nt][2]), "+f"(acc[mt][nt][3])
                        : "r"(af[mt][0]), "r"(af[mt][1]), "r"(af[mt][2]), "r"(af[mt][3]),
                          "r"(bf[nt][0]), "r"(bf[nt][1]));
                }
        }
        __syncthreads();
    }

    const size_t colBase = (size_t)(gate * MEM_SZ + n0in);
    #pragma unroll
    for (int mt = 0; mt < 4; mt++) {
        int r0 = m0 + wmB + mt * 16 + g;
        #pragma unroll
        for (int nt = 0; nt < 4; nt++) {
            size_t co = colBase + wnB + nt * 8 + cq * 2;
            if (r0 < M) {
                float2 v = make_float2(acc[mt][nt][0], acc[mt][nt][1]);
                *(float2*)&Out[(size_t)r0 * NFUSED + co] = v;
            }
            if (r0 + 8 < M) {
                float2 v = make_float2(acc[mt][nt][2], acc[mt][nt][3]);
                *(float2*)&Out[(size_t)(r0 + 8) * NFUSED + co] = v;
            }
        }
    }
}

// ---------------------------------------------------------------------------
// Main gate update, one step; writes channels-last fp16 h
// ---------------------------------------------------------------------------
__global__ void gate_step(int t, const float* __restrict__ bfi,
                          const float* __restrict__ bc, const float* __restrict__ bo) {
    int lin = blockIdx.x * 256 + threadIdx.x;
    if (lin >= MSTEP * MEM_SZ) return;
    int n = lin & (MEM_SZ - 1);
    int m = lin >> 9;
    int b = m / HW, hw = m - HW * b;
    size_t bigOff = ((size_t)t * MSTEP + m) * NFUSED;
    size_t hOff   = (size_t)m * NFUSED;
    float pfi = g_preM[bigOff + n]        + g_hpre[hOff + n]        + bfi[n];
    float pc  = g_preM[bigOff + 512 + n]  + g_hpre[hOff + 512 + n]  + bc[n];
    float po  = g_preM[bigOff + 1024 + n] + g_hpre[hOff + 1024 + n] + bo[n];
    float fi = sigmoidf_(pfi);
    float o  = sigmoidf_(po);
    float cn = fi * g_cstate[lin] + (1.0f - fi) * tanhf(pc);
    g_cstate[lin] = cn;
    float h = o * tanhf(cn);
    int p = (hw / 7 + 1) * 9 + (hw % 7) + 1;
    g_hT[(size_t)b * HROW + (size_t)p * MEM_SZ + n] = __float2half_rn(h);
}

// ---------------------------------------------------------------------------
// Final: feats = mean_hw(h); logits = feats @ W_fc^T + b_fc
// ---------------------------------------------------------------------------
__global__ void final_kernel(const float* __restrict__ W_fc, const float* __restrict__ b_fc,
                             float* __restrict__ logitsOut, float* __restrict__ featsOut) {
    int b = blockIdx.x, n = threadIdx.x;
    const __half* hb = &g_hT[(size_t)b * HROW];
    float s = 0.f;
    #pragma unroll
    for (int hh = 1; hh <= 7; hh++)
        #pragma unroll
        for (int ww = 1; ww <= 7; ww++) s += __half2float(hb[(size_t)(hh * 9 + ww) * MEM_SZ + n]);
    float f = s * (1.0f / 49.0f);
    __shared__ float fs[MEM_SZ];
    fs[n] = f;
    if (featsOut) featsOut[b * MEM_SZ + n] = f;
    __syncthreads();
    if (n < N_CLS && logitsOut) {
        float acc = b_fc[n];
        for (int k = 0; k < MEM_SZ; k++) acc += fs[k] * W_fc[n * MEM_SZ + k];
        logitsOut[b * N_CLS + n] = acc;
    }
}

// ---------------------------------------------------------------------------
// Host launcher
// ---------------------------------------------------------------------------
extern "C" void kernel_launch(void* const* d_in, const int* in_sizes, int n_in,
                              void* d_out, int out_size) {
    const float* x     = (const float*)d_in[0];
    const float* W_fi  = (const float*)d_in[1];
    const float* b_fi  = (const float*)d_in[2];
    const float* W_c   = (const float*)d_in[3];
    const float* b_c   = (const float*)d_in[4];
    const float* W_o   = (const float*)d_in[5];
    const float* b_o   = (const float*)d_in[6];
    const float* Ws_fi = (const float*)d_in[7];
    const float* bs_fi = (const float*)d_in[8];
    const float* Ws_c  = (const float*)d_in[9];
    const float* bs_c  = (const float*)d_in[10];
    const float* Ws_o  = (const float*)d_in[11];
    const float* bs_o  = (const float*)d_in[12];
    const float* W_cam = (const float*)d_in[13];
    const float* W_fc  = (const float*)d_in[14];
    const float* b_fc  = (const float*)d_in[15];

    __half* xT; cudaGetSymbolAddress((void**)&xT, g_xT);
    __half* hT; cudaGetSymbolAddress((void**)&hT, g_hT);
    __half* wx; cudaGetSymbolAddress((void**)&wx, g_wx);
    __half* wh; cudaGetSymbolAddress((void**)&wh, g_wh);
    float*  pm; cudaGetSymbolAddress((void**)&pm, g_preM);
    float*  hp; cudaGetSymbolAddress((void**)&hp, g_hpre);

    const int SMEM_BYTES = PIPE * STGB;   // 98304
    cudaFuncSetAttribute(conv_gemm_fp16, cudaFuncAttributeMaxDynamicSharedMemorySize, SMEM_BYTES);

    float* outF = (float*)d_out;
    float* lp = nullptr; float* fp = nullptr;
    if (out_size >= B_SZ * N_CLS + B_SZ * MEM_SZ) { lp = outF; fp = outF + B_SZ * N_CLS; }
    else if (out_size == B_SZ * MEM_SZ)           { fp = outF; }
    else                                          { lp = outF; }

    // 1. reset recurrent state; zero xT borders
    zero_states<<<(B_SZ * HROW + 255) / 256, 256>>>();
    border_zero<<<(int)(((size_t)TB * 32 * C_IN + 255) / 256), 256>>>();
    // 2. transpose + pad input to fp16; reorder weights to fp16
    {
        dim3 grid(TB, C_IN / 32);
        pad_xT<<<grid, 256>>>(x);
    }
    reorder_wx<<<(int)(((size_t)3 * MEM_SZ * C_IN + 255) / 256), 256>>>(W_fi, W_c, W_o);
    reorder_wh<<<(int)(((size_t)3 * MEM_SZ * MEM_SZ + 255) / 256), 256>>>(W_fi, W_c, W_o);
    reorder_ws<<<(3 * C_IN + 255) / 256, 256>>>(Ws_fi, Ws_c, Ws_o);
    // 3. attention-gate x contributions
    preS_kernel<<<TB, 256>>>();
    // 4. CAM pipeline
    pooled_kernel<<<(TB * C_IN + 255) / 256, 256>>>(x);
    cam_logits_kernel<<<(TB * C_CAM + 3) / 4, 128>>>(W_cam);
    argmax_kernel<<<TB, 256>>>();
    cam_kernel<<<(TB * HW + 7) / 8, 256>>>(x, W_cam);
    cam_softmax_kernel<<<TB, 64>>>();
    // 5. fused attention recurrence
    att_fused<<<B_SZ, 64>>>(Ws_fi, Ws_c, Ws_o, bs_fi, bs_c, bs_o);
    // 6. attention scaling
    scale_x<<<(int)(((size_t)TB * HW * C_IN + 255) / 256), 256>>>();
    // 7. giant parallel GEMM (x part, all t, 3 gates)
    {
        dim3 grid(12, MBIG / 128);   // n-blocks fast -> B L2-resident per wave
        conv_gemm_fp16<<<grid, 256, SMEM_BYTES>>>(xT, C_IN, 11, MBIG, KX / 64, KX, wx, pm);
    }
    // 8. sequential main recurrence
    for (int t = 0; t < T_STEPS; t++) {
        dim3 grid(12, (MSTEP + 127) / 128);
        conv_gemm_fp16<<<grid, 256, SMEM_BYTES>>>(hT, MEM_SZ, 9, MSTEP, KH / 64, KH, wh, hp);
        gate_step<<<(MSTEP * MEM_SZ + 255) / 256, 256>>>(t, b_fi, b_c, b_o);
    }
    // 9. final pooling + FC head
    final_kernel<<<B_SZ, MEM_SZ>>>(W_fc, b_fc, lp, fp);
}

// round 9
// speedup vs baseline: 18.7701x; 1.0082x over previous
#include <cuda_runtime.h>
#include <cuda_fp16.h>
#include <math.h>
#include <stdint.h>

// ---------------------------------------------------------------------------
// Problem dims
// ---------------------------------------------------------------------------
#define T_STEPS 16
#define B_SZ    32
#define C_IN    2048
#define MEM_SZ  512
#define N_CLS   8
#define C_CAM   1000
#define HW      49
#define PADHW   81
#define KX      (C_IN*9)          // 18432
#define KH      (MEM_SZ*9)        // 4608
#define WROW    ((C_IN+MEM_SZ)*9) // 23040 original main-weight row stride
#define MBIG    (T_STEPS*B_SZ*HW) // 25088
#define MSTEP   (B_SZ*HW)         // 1568
#define TB      (T_STEPS*B_SZ)    // 512
#define NFUSED  (3*MEM_SZ)        // 1536
#define XROW    (PADHW*C_IN)      // halves per tb in xT
#define HROW    (PADHW*MEM_SZ)    // halves per b in hT

// ---------------------------------------------------------------------------
// Static device scratch (fp16 GEMM operands, fp32 elsewhere)
// ---------------------------------------------------------------------------
__device__ __half g_xT[(size_t)TB * XROW];
__device__ __half g_hT[B_SZ * HROW];
__device__ __half g_wx[(size_t)3 * MEM_SZ * KX];
__device__ __half g_wh[(size_t)3 * MEM_SZ * KH];
__device__ float  g_wsx[3 * KX];
__device__ float  g_preS0[MBIG];
__device__ float  g_preS1[MBIG];
__device__ float  g_preS2[MBIG];
__device__ float  g_attmap[MBIG];
__device__ float  g_s[MBIG];
__device__ float  g_pooled[TB * C_IN];
__device__ float  g_logits[TB * C_CAM];
__device__ int    g_idx[TB];
__device__ float  g_cam[TB * HW];
__device__ float  g_preM[(size_t)MBIG * NFUSED];
__device__ float  g_hpre[(size_t)MSTEP * NFUSED];
__device__ float  g_cstate[MSTEP * MEM_SZ];

__constant__ int c_border[32] = {
    0,1,2,3,4,5,6,7,8,
    72,73,74,75,76,77,78,79,80,
    9,17, 18,26, 27,35, 36,44, 45,53, 54,62, 63,71
};

__device__ __forceinline__ float sigmoidf_(float x) { return 1.0f / (1.0f + expf(-x)); }

// ---------------------------------------------------------------------------
// Zero recurrent states (incl. g_hpre so step-0 h-GEMM can be skipped)
// ---------------------------------------------------------------------------
__global__ void zero_states() {
    int i = blockIdx.x * 256 + threadIdx.x;
    if (i < B_SZ * HROW)     g_hT[i] = __float2half_rn(0.f);
    if (i < MSTEP * MEM_SZ)  g_cstate[i] = 0.f;
    if (i < MSTEP * NFUSED)  g_hpre[i] = 0.f;
}

// ---------------------------------------------------------------------------
// Zero border positions of xT
// ---------------------------------------------------------------------------
__global__ void border_zero() {
    size_t lin = (size_t)blockIdx.x * 256 + threadIdx.x;
    if (lin >= (size_t)TB * 32 * C_IN) return;
    int c  = lin & (C_IN - 1);
    int r  = (int)(lin >> 11);
    int bp = r & 31;
    int tb = r >> 5;
    g_xT[(size_t)tb * XROW + c_border[bp] * C_IN + c] = __float2half_rn(0.f);
}

// ---------------------------------------------------------------------------
// Transpose NCHW x -> channels-last padded fp16 xT
// ---------------------------------------------------------------------------
__global__ void pad_xT(const float* __restrict__ x) {
    __shared__ float tile[32][50];
    int tb = blockIdx.x, c0 = blockIdx.y * 32;
    int tid = threadIdx.x;
    for (int idx = tid; idx < 32 * HW; idx += 256) {
        int r = idx / HW, q = idx - HW * r;
        tile[r][q] = x[((size_t)tb * C_IN + c0 + r) * HW + q];
    }
    __syncthreads();
    for (int idx = tid; idx < HW * 32; idx += 256) {
        int q = idx >> 5, cl = idx & 31;
        int p = (q / 7 + 1) * 9 + (q % 7) + 1;
        g_xT[(size_t)tb * XROW + (size_t)p * C_IN + c0 + cl] = __float2half_rn(tile[cl][q]);
    }
}

// ---------------------------------------------------------------------------
// Weight reorders: (c,kh,kw) -> (tap, c), fp16
// ---------------------------------------------------------------------------
__global__ void reorder_wx(const float* __restrict__ W0, const float* __restrict__ W1,
                           const float* __restrict__ W2) {
    size_t lin = (size_t)blockIdx.x * 256 + threadIdx.x;
    if (lin >= (size_t)3 * MEM_SZ * C_IN) return;
    int c = lin & (C_IN - 1);
    int r = (int)(lin >> 11);
    int n = r & (MEM_SZ - 1);
    int gate = r >> 9;
    const float* W = (gate == 0) ? W0 : (gate == 1 ? W1 : W2);
    const float* src = W + (size_t)n * WROW + (size_t)c * 9;
    __half* dst = g_wx + ((size_t)gate * MEM_SZ + n) * KX + c;
    #pragma unroll
    for (int tap = 0; tap < 9; tap++) dst[(size_t)tap * C_IN] = __float2half_rn(src[tap]);
}

__global__ void reorder_wh(const float* __restrict__ W0, const float* __restrict__ W1,
                           const float* __restrict__ W2) {
    size_t lin = (size_t)blockIdx.x * 256 + threadIdx.x;
    if (lin >= (size_t)3 * MEM_SZ * MEM_SZ) return;
    int c = lin & (MEM_SZ - 1);
    int r = (int)(lin >> 9);
    int n = r & (MEM_SZ - 1);
    int gate = r >> 9;
    const float* W = (gate == 0) ? W0 : (gate == 1 ? W1 : W2);
    const float* src = W + (size_t)n * WROW + (size_t)(C_IN + c) * 9;
    __half* dst = g_wh + ((size_t)gate * MEM_SZ + n) * KH + c;
    #pragma unroll
    for (int tap = 0; tap < 9; tap++) dst[(size_t)tap * MEM_SZ] = __float2half_rn(src[tap]);
}

__global__ void reorder_ws(const float* __restrict__ Wsfi, const float* __restrict__ Wsc,
                           const float* __restrict__ Wso) {
    int lin = blockIdx.x * 256 + threadIdx.x;
    if (lin >= 3 * C_IN) return;
    int gate = lin >> 11, c = lin & (C_IN - 1);
    const float* W = (gate == 0) ? Wsfi : (gate == 1 ? Wsc : Wso);
    #pragma unroll
    for (int tap = 0; tap < 9; tap++)
        g_wsx[gate * KX + tap * C_IN + c] = W[c * 9 + tap];
}

// ---------------------------------------------------------------------------
// Attention-gate x contributions (fp32 math, fp16 x reads)
// ---------------------------------------------------------------------------
__global__ __launch_bounds__(256) void preS_kernel() {
    int tb = blockIdx.x;
    int tid = threadIdx.x;
    int wid = tid >> 5, lane = tid & 31;
    __shared__ float ws[3 * C_IN];

    float acc[7][3];
    #pragma unroll
    for (int j = 0; j < 7; j++) { acc[j][0] = 0.f; acc[j][1] = 0.f; acc[j][2] = 0.f; }

    const __half* xb = g_xT + (size_t)tb * XROW;

    for (int tap = 0; tap < 9; tap++) {
        __syncthreads();
        for (int idx = tid; idx < 3 * C_IN; idx += 256) {
            int g = idx >> 11, c = idx & (C_IN - 1);
            ws[idx] = g_wsx[g * KX + tap * C_IN + c];
        }
        __syncthreads();
        int dr = tap / 3, dc = tap - 3 * dr;
        #pragma unroll
        for (int j = 0; j < 7; j++) {
            int hw = wid + 8 * j;
            if (hw >= HW) break;
            int hh = hw / 7, ww = hw - 7 * hh;
            const __half* xr = xb + (size_t)((hh + dr) * 9 + ww + dc) * C_IN;
            float a0 = 0.f, a1 = 0.f, a2 = 0.f;
            for (int c = lane; c < C_IN; c += 32) {
                float v = __half2float(xr[c]);
                a0 += v * ws[c];
                a1 += v * ws[C_IN + c];
                a2 += v * ws[2 * C_IN + c];
            }
            acc[j][0] += a0; acc[j][1] += a1; acc[j][2] += a2;
        }
    }
    #pragma unroll
    for (int j = 0; j < 7; j++) {
        int hw = wid + 8 * j;
        if (hw >= HW) break;
        float a0 = acc[j][0], a1 = acc[j][1], a2 = acc[j][2];
        #pragma unroll
        for (int o = 16; o > 0; o >>= 1) {
            a0 += __shfl_down_sync(0xffffffffu, a0, o);
            a1 += __shfl_down_sync(0xffffffffu, a1, o);
            a2 += __shfl_down_sync(0xffffffffu, a2, o);
        }
        if (lane == 0) {
            int m = tb * HW + hw;
            g_preS0[m] = a0; g_preS1[m] = a1; g_preS2[m] = a2;
        }
    }
}

// ---------------------------------------------------------------------------
// CAM pipeline (raw NCHW x)
// ---------------------------------------------------------------------------
__global__ void pooled_kernel(const float* __restrict__ x) {
    int lin = blockIdx.x * 256 + threadIdx.x;
    if (lin >= TB * C_IN) return;
    const float* p = x + (size_t)lin * HW;
    float s = 0.f;
    #pragma unroll
    for (int i = 0; i < HW; i++) s += p[i];
    g_pooled[lin] = s * (1.0f / 49.0f);
}

__global__ void cam_logits_kernel(const float* __restrict__ W_cam) {
    int gw   = blockIdx.x * 4 + (threadIdx.x >> 5);
    int lane = threadIdx.x & 31;
    if (gw >= TB * C_CAM) return;
    int tb = gw / C_CAM, j = gw % C_CAM;
    const float* p  = &g_pooled[tb * C_IN];
    const float* wr = &W_cam[(size_t)j * C_IN];
    float acc = 0.f;
    for (int c = lane; c < C_IN; c += 32) acc += p[c] * wr[c];
    #pragma unroll
    for (int o = 16; o > 0; o >>= 1) acc += __shfl_down_sync(0xffffffffu, acc, o);
    if (lane == 0) g_logits[gw] = acc;
}

__global__ void argmax_kernel() {
    int tb = blockIdx.x, tid = threadIdx.x;
    float best = -INFINITY; int bi = 0;
    for (int j = tid; j < C_CAM; j += 256) {
        float v = g_logits[tb * C_CAM + j];
        if (v > best) { best = v; bi = j; }
    }
    __shared__ float sv[256]; __shared__ int si[256];
    sv[tid] = best; si[tid] = bi; __syncthreads();
    for (int s = 128; s > 0; s >>= 1) {
        if (tid < s) {
            float v2 = sv[tid + s]; int i2 = si[tid + s];
            if (v2 > sv[tid] || (v2 == sv[tid] && i2 < si[tid])) { sv[tid] = v2; si[tid] = i2; }
        }
        __syncthreads();
    }
    if (tid == 0) g_idx[tb] = si[0];
}

__global__ void cam_kernel(const float* __restrict__ x, const float* __restrict__ W_cam) {
    int gw   = blockIdx.x * 8 + (threadIdx.x >> 5);
    int lane = threadIdx.x & 31;
    if (gw >= TB * HW) return;
    int tb = gw / HW, hw = gw % HW;
    const float* wsel = &W_cam[(size_t)g_idx[tb] * C_IN];
    const float* xp   = x + (size_t)tb * C_IN * HW + hw;
    float acc = 0.f;
    for (int c = lane; c < C_IN; c += 32) acc += wsel[c] * xp[(size_t)c * HW];
    #pragma unroll
    for (int o = 16; o > 0; o >>= 1) acc += __shfl_down_sync(0xffffffffu, acc, o);
    if (lane == 0) g_cam[gw] = acc;
}

__global__ void cam_softmax_kernel() {
    int tb = blockIdx.x, tid = threadIdx.x;
    __shared__ float v[HW]; __shared__ float red[64];
    if (tid < HW) v[tid] = g_cam[tb * HW + tid];
    __syncthreads();
    float m = (tid < HW) ? v[tid] : -INFINITY;
    red[tid] = m; __syncthreads();
    for (int s = 32; s > 0; s >>= 1) { if (tid < s) red[tid] = fmaxf(red[tid], red[tid + s]); __syncthreads(); }
    float mx = red[0]; __syncthreads();
    float e = (tid < HW) ? expf(v[tid] - mx) : 0.f;
    red[tid] = e; __syncthreads();
    for (int s = 32; s > 0; s >>= 1) { if (tid < s) red[tid] += red[tid + s]; __syncthreads(); }
    if (tid < HW) g_attmap[tb * HW + tid] = e / red[0];
}

// ---------------------------------------------------------------------------
// Fused attention recurrence
// ---------------------------------------------------------------------------
__global__ void att_fused(const float* __restrict__ Wfi, const float* __restrict__ Wc,
                          const float* __restrict__ Wo,
                          const float* __restrict__ bfi, const float* __restrict__ bc,
                          const float* __restrict__ bo) {
    int b = blockIdx.x, tid = threadIdx.x;
    __shared__ float ap[HW], av[HW], csh[HW], red[64];
    if (tid < HW) { ap[tid] = 0.f; csh[tid] = 0.f; }
    __syncthreads();
    for (int t = 0; t < T_STEPS; t++) {
        if (tid < HW) {
            int h = tid / 7, w = tid % 7;
            float efi = 0.f, ec = 0.f, eo = 0.f;
            #pragma unroll
            for (int kh = 0; kh < 3; kh++)
                #pragma unroll
                for (int kw = 0; kw < 3; kw++) {
                    int hh = h + kh - 1, ww = w + kw - 1;
                    if (hh >= 0 && hh < 7 && ww >= 0 && ww < 7) {
                        float aval = ap[hh * 7 + ww];
                        int off = KX + kh * 3 + kw;
                        efi += aval * Wfi[off];
                        ec  += aval * Wc[off];
                        eo  += aval * Wo[off];
                    }
                }
            int base = (t * B_SZ + b) * HW + tid;
            float fi = sigmoidf_(g_preS0[base] + efi + bfi[0]);
            float o  = sigmoidf_(g_preS2[base] + eo + bo[0]);
            float cc = tanhf(g_preS1[base] + ec + bc[0]);
            float cs = fi * csh[tid] + (1.0f - fi) * cc;
            csh[tid] = cs;
            av[tid] = o * tanhf(cs) * g_attmap[base];
        }
        __syncthreads();
        float m = (tid < HW) ? av[tid] : -INFINITY;
        red[tid] = m; __syncthreads();
        for (int s = 32; s > 0; s >>= 1) { if (tid < s) red[tid] = fmaxf(red[tid], red[tid + s]); __syncthreads(); }
        float mx = red[0]; __syncthreads();
        float e = (tid < HW) ? expf(av[tid] - mx) : 0.f;
        red[tid] = e; __syncthreads();
        for (int s = 32; s > 0; s >>= 1) { if (tid < s) red[tid] += red[tid + s]; __syncthreads(); }
        if (tid < HW) {
            g_s[(t * B_SZ + b) * HW + tid] = e / red[0];
            ap[tid] = av[tid];
        }
        __syncthreads();
    }
}

// ---------------------------------------------------------------------------
// x_att scaling (coalesced over c), fp16 in/out
// ---------------------------------------------------------------------------
__global__ void scale_x() {
    size_t lin = (size_t)blockIdx.x * 256 + threadIdx.x;
    if (lin >= (size_t)TB * HW * C_IN) return;
    int c  = lin & (C_IN - 1);
    int rc = (int)(lin >> 11);
    int tb = rc / HW, hw = rc - HW * tb;
    float sc = g_s[rc];
    int p = (hw / 7 + 1) * 9 + (hw % 7) + 1;
    size_t a = (size_t)tb * XROW + (size_t)p * C_IN + c;
    g_xT[a] = __float2half_rn(__half2float(g_xT[a]) * sc);
}

// ---------------------------------------------------------------------------
// FP16 implicit GEMM, 128(M)x128(N)x64(K), 8 warps (2x4), warp 64x32.
// Used for the sequential h-chain (small M). 3-stage cp.async, XOR swizzle.
// ---------------------------------------------------------------------------
#define STGB 32768
#define PIPE 3

__global__ __launch_bounds__(256, 2) void conv_gemm_fp16(
    const __half* __restrict__ Apad, int Crow, int cshift, int M, int KT, int Kfull,
    const __half* __restrict__ Wbase, float* __restrict__ Out)
{
    extern __shared__ char smc[];
    const int tid  = threadIdx.x;
    const int m0   = blockIdx.y * 128;
    const int gate = blockIdx.x >> 2;
    const int n0in = (blockIdx.x & 3) * 128;
    const __half* Wg = Wbase + ((size_t)gate * MEM_SZ + n0in) * Kfull;

    const int rlo = tid >> 3;
    const int kq  = (tid & 7) * 8;
    const int stChunk = ((tid & 7) ^ (rlo & 7)) << 4;

    size_t rowoff[4]; int asz[4];
    #pragma unroll
    for (int i = 0; i < 4; i++) {
        int m = m0 + rlo + 32 * i;
        if (m < M) {
            int tb = m / HW, hw = m - HW * tb;
            rowoff[i] = ((size_t)tb * PADHW + (size_t)((hw / 7) * 9 + hw % 7)) * Crow;
            asz[i] = 16;
        } else { rowoff[i] = 0; asz[i] = 0; }
    }

    const int lane = tid & 31;
    const int wid  = tid >> 5;
    const int g    = lane >> 2;
    const int cq   = lane & 3;
    const int wmB  = (wid & 1) * 64;
    const int wnB  = (wid >> 1) * 32;

    float acc[4][4][4];
    #pragma unroll
    for (int a = 0; a < 4; a++)
        #pragma unroll
        for (int b = 0; b < 4; b++)
            #pragma unroll
            for (int c = 0; c < 4; c++) acc[a][b][c] = 0.f;

    auto issue = [&](int s, int kt) {
        char* As_ = smc + s * STGB;
        char* Bs_ = As_ + 16384;
        uint32_t aB = (uint32_t)__cvta_generic_to_shared(As_);
        uint32_t bB = (uint32_t)__cvta_generic_to_shared(Bs_);
        int k0  = kt * 64;
        int tap = k0 >> cshift;
        int c0  = k0 & (Crow - 1);
        int dr  = tap / 3, dc = tap - 3 * dr;
        size_t poff = (size_t)(dr * 9 + dc) * Crow + c0 + kq;
        #pragma unroll
        for (int i = 0; i < 4; i++) {
            const __half* src = Apad + rowoff[i] + poff;
            uint32_t dst = aB + (uint32_t)((rlo + 32 * i) * 128 + stChunk);
            asm volatile("cp.async.cg.shared.global [%0], [%1], 16, %2;\n"
                         :: "r"(dst), "l"(src), "r"(asz[i]));
        }
        #pragma unroll
        for (int i = 0; i < 4; i++) {
            int nl = rlo + 32 * i;
            const __half* src = Wg + (size_t)nl * Kfull + k0 + kq;
            uint32_t dst = bB + (uint32_t)(nl * 128 + stChunk);
            asm volatile("cp.async.cg.shared.global [%0], [%1], 16;\n"
                         :: "r"(dst), "l"(src));
        }
        asm volatile("cp.async.commit_group;\n");
    };

    #pragma unroll
    for (int s = 0; s < PIPE - 1; s++)
        if (s < KT) issue(s, s);

    for (int kt = 0; kt < KT; kt++) {
        if (kt + 1 < KT) asm volatile("cp.async.wait_group 1;\n" ::: "memory");
        else             asm volatile("cp.async.wait_group 0;\n" ::: "memory");
        __syncthreads();
        if (kt + PIPE - 1 < KT) issue((kt + PIPE - 1) % PIPE, kt + PIPE - 1);

        const char* As_ = smc + (kt % PIPE) * STGB;
        const char* Bs_ = As_ + 16384;

        #pragma unroll
        for (int ks = 0; ks < 4; ks++) {
            const int ch0 = (((2 * ks)     ^ g) << 4) + 4 * cq;
            const int ch1 = (((2 * ks + 1) ^ g) << 4) + 4 * cq;
            unsigned af[4][4], bf[4][2];
            #pragma unroll
            for (int mt = 0; mt < 4; mt++) {
                const char* r0p = As_ + (wmB + mt * 16 + g) * 128;
                const char* r1p = r0p + 8 * 128;
                af[mt][0] = *(const uint32_t*)(r0p + ch0);
                af[mt][1] = *(const uint32_t*)(r1p + ch0);
                af[mt][2] = *(const uint32_t*)(r0p + ch1);
                af[mt][3] = *(const uint32_t*)(r1p + ch1);
            }
            #pragma unroll
            for (int nt = 0; nt < 4; nt++) {
                const char* np = Bs_ + (wnB + nt * 8 + g) * 128;
                bf[nt][0] = *(const uint32_t*)(np + ch0);
                bf[nt][1] = *(const uint32_t*)(np + ch1);
            }
            #pragma unroll
            for (int mt = 0; mt < 4; mt++)
                #pragma unroll
                for (int nt = 0; nt < 4; nt++) {
                    asm volatile(
                        "mma.sync.aligned.m16n8k16.row.col.f32.f16.f16.f32 "
                        "{%0,%1,%2,%3}, {%4,%5,%6,%7}, {%8,%9}, {%0,%1,%2,%3};\n"
                        : "+f"(acc[mt][nt][0]), "+f"(acc[mt][nt][1]),
                          "+f"(acc[mt][nt][2]), "+f"(acc[mt][nt][3])
                        : "r"(af[mt][0]), "r"(af[mt][1]), "r"(af[mt][2]), "r"(af[mt][3]),
                          "r"(bf[nt][0]), "r"(bf[nt][1]));
                }
        }
        __syncthreads();
    }

    const size_t colBase = (size_t)(gate * MEM_SZ + n0in);
    #pragma unroll
    for (int mt = 0; mt < 4; mt++) {
        int r0 = m0 + wmB + mt * 16 + g;
        #pragma unroll
        for (int nt = 0; nt < 4; nt++) {
            size_t co = colBase + wnB + nt * 8 + cq * 2;
            if (r0 < M) {
                float2 v = make_float2(acc[mt][nt][0], acc[mt][nt][1]);
                *(float2*)&Out[(size_t)r0 * NFUSED + co] = v;
            }
            if (r0 + 8 < M) {
                float2 v = make_float2(acc[mt][nt][2], acc[mt][nt][3]);
                *(float2*)&Out[(size_t)(r0 + 8) * NFUSED + co] = v;
            }
        }
    }
}

// ---------------------------------------------------------------------------
// FP16 implicit GEMM, 256(M)x128(N)x64(K), 8 warps (4m x 2n), warp 64x64.
// Big-M kernel: halves L2 feed per FLOP (24 B/cyc/SM) -> HMMA-bound.
// ---------------------------------------------------------------------------
#define STGB2 49152   // 32KB A (256x64 halves) + 16KB B (128x64 halves)

__global__ __launch_bounds__(256, 1) void conv_gemm_fp16_m256(
    const __half* __restrict__ Apad, int Crow, int cshift, int M, int KT, int Kfull,
    const __half* __restrict__ Wbase, float* __restrict__ Out)
{
    extern __shared__ char smc[];
    const int tid  = threadIdx.x;
    const int m0   = blockIdx.y * 256;
    const int gate = blockIdx.x >> 2;
    const int n0in = (blockIdx.x & 3) * 128;
    const __half* Wg = Wbase + ((size_t)gate * MEM_SZ + n0in) * Kfull;

    const int rlo = tid >> 3;            // 0..31
    const int kq  = (tid & 7) * 8;
    const int stChunk = ((tid & 7) ^ (rlo & 7)) << 4;

    size_t rowoff[8]; int asz[8];
    #pragma unroll
    for (int i = 0; i < 8; i++) {
        int m = m0 + rlo + 32 * i;
        if (m < M) {
            int tb = m / HW, hw = m - HW * tb;
            rowoff[i] = ((size_t)tb * PADHW + (size_t)((hw / 7) * 9 + hw % 7)) * Crow;
            asz[i] = 16;
        } else { rowoff[i] = 0; asz[i] = 0; }
    }

    const int lane = tid & 31;
    const int wid  = tid >> 5;
    const int g    = lane >> 2;
    const int cq   = lane & 3;
    const int wmB  = (wid & 3) * 64;     // 4 m-warps
    const int wnB  = (wid >> 2) * 64;    // 2 n-warps

    float acc[4][8][4];
    #pragma unroll
    for (int a = 0; a < 4; a++)
        #pragma unroll
        for (int b = 0; b < 8; b++)
            #pragma unroll
            for (int c = 0; c < 4; c++) acc[a][b][c] = 0.f;

    auto issue = [&](int s, int kt) {
        char* As_ = smc + s * STGB2;
        char* Bs_ = As_ + 32768;
        uint32_t aB = (uint32_t)__cvta_generic_to_shared(As_);
        uint32_t bB = (uint32_t)__cvta_generic_to_shared(Bs_);
        int k0  = kt * 64;
        int tap = k0 >> cshift;
        int c0  = k0 & (Crow - 1);
        int dr  = tap / 3, dc = tap - 3 * dr;
        size_t poff = (size_t)(dr * 9 + dc) * Crow + c0 + kq;
        #pragma unroll
        for (int i = 0; i < 8; i++) {
            const __half* src = Apad + rowoff[i] + poff;
            uint32_t dst = aB + (uint32_t)((rlo + 32 * i) * 128 + stChunk);
            asm volatile("cp.async.cg.shared.global [%0], [%1], 16, %2;\n"
                         :: "r"(dst), "l"(src), "r"(asz[i]));
        }
        #pragma unroll
        for (int i = 0; i < 4; i++) {
            int nl = rlo + 32 * i;
            const __half* src = Wg + (size_t)nl * Kfull + k0 + kq;
            uint32_t dst = bB + (uint32_t)(nl * 128 + stChunk);
            asm volatile("cp.async.cg.shared.global [%0], [%1], 16;\n"
                         :: "r"(dst), "l"(src));
        }
        asm volatile("cp.async.commit_group;\n");
    };

    #pragma unroll
    for (int s = 0; s < PIPE - 1; s++)
        if (s < KT) issue(s, s);

    for (int kt = 0; kt < KT; kt++) {
        if (kt + 1 < KT) asm volatile("cp.async.wait_group 1;\n" ::: "memory");
        else             asm volatile("cp.async.wait_group 0;\n" ::: "memory");
        __syncthreads();
        if (kt + PIPE - 1 < KT) issue((kt + PIPE - 1) % PIPE, kt + PIPE - 1);

        const char* As_ = smc + (kt % PIPE) * STGB2;
        const char* Bs_ = As_ + 32768;

        #pragma unroll
        for (int ks = 0; ks < 4; ks++) {
            const int ch0 = (((2 * ks)     ^ g) << 4) + 4 * cq;
            const int ch1 = (((2 * ks + 1) ^ g) << 4) + 4 * cq;
            unsigned af[4][4], bf[8][2];
            #pragma unroll
            for (int mt = 0; mt < 4; mt++) {
                const char* r0p = As_ + (wmB + mt * 16 + g) * 128;
                const char* r1p = r0p + 8 * 128;
                af[mt][0] = *(const uint32_t*)(r0p + ch0);
                af[mt][1] = *(const uint32_t*)(r1p + ch0);
                af[mt][2] = *(const uint32_t*)(r0p + ch1);
                af[mt][3] = *(const uint32_t*)(r1p + ch1);
            }
            #pragma unroll
            for (int nt = 0; nt < 8; nt++) {
                const char* np = Bs_ + (wnB + nt * 8 + g) * 128;
                bf[nt][0] = *(const uint32_t*)(np + ch0);
                bf[nt][1] = *(const uint32_t*)(np + ch1);
            }
            #pragma unroll
            for (int mt = 0; mt < 4; mt++)
                #pragma unroll
                for (int nt = 0; nt < 8; nt++) {
                    asm volatile(
                        "mma.sync.aligned.m16n8k16.row.col.f32.f16.f16.f32 "
                        "{%0,%1,%2,%3}, {%4,%5,%6,%7}, {%8,%9}, {%0,%1,%2,%3};\n"
                        : "+f"(acc[mt][nt][0]), "+f"(acc[mt][nt][1]),
                          "+f"(acc[mt][nt][2]), "+f"(acc[mt][nt][3])
                        : "r"(af[mt][0]), "r"(af[mt][1]), "r"(af[mt][2]), "r"(af[mt][3]),
                          "r"(bf[nt][0]), "r"(bf[nt][1]));
                }
        }
        __syncthreads();
    }

    const size_t colBase = (size_t)(gate * MEM_SZ + n0in);
    #pragma unroll
    for (int mt = 0; mt < 4; mt++) {
        int r0 = m0 + wmB + mt * 16 + g;
        #pragma unroll
        for (int nt = 0; nt < 8; nt++) {
            size_t co = colBase + wnB + nt * 8 + cq * 2;
            if (r0 < M) {
                float2 v = make_float2(acc[mt][nt][0], acc[mt][nt][1]);
                *(float2*)&Out[(size_t)r0 * NFUSED + co] = v;
            }
            if (r0 + 8 < M) {
                float2 v = make_float2(acc[mt][nt][2], acc[mt][nt][3]);
                *(float2*)&Out[(size_t)(r0 + 8) * NFUSED + co] = v;
            }
        }
    }
}

// ---------------------------------------------------------------------------
// Main gate update, one step; writes channels-last fp16 h
// ---------------------------------------------------------------------------
__global__ void gate_step(int t, const float* __restrict__ bfi,
                          const float* __restrict__ bc, const float* __restrict__ bo) {
    int lin = blockIdx.x * 256 + threadIdx.x;
    if (lin >= MSTEP * MEM_SZ) return;
    int n = lin & (MEM_SZ - 1);
    int m = lin >> 9;
    int b = m / HW, hw = m - HW * b;
    size_t bigOff = ((size_t)t * MSTEP + m) * NFUSED;
    size_t hOff   = (size_t)m * NFUSED;
    float pfi = g_preM[bigOff + n]        + g_hpre[hOff + n]        + bfi[n];
    float pc  = g_preM[bigOff + 512 + n]  + g_hpre[hOff + 512 + n]  + bc[n];
    float po  = g_preM[bigOff + 1024 + n] + g_hpre[hOff + 1024 + n] + bo[n];
    float fi = sigmoidf_(pfi);
    float o  = sigmoidf_(po);
    float cn = fi * g_cstate[lin] + (1.0f - fi) * tanhf(pc);
    g_cstate[lin] = cn;
    float h = o * tanhf(cn);
    int p = (hw / 7 + 1) * 9 + (hw % 7) + 1;
    g_hT[(size_t)b * HROW + (size_t)p * MEM_SZ + n] = __float2half_rn(h);
}

// ---------------------------------------------------------------------------
// Final: feats = mean_hw(h); logits = feats @ W_fc^T + b_fc
// ---------------------------------------------------------------------------
__global__ void final_kernel(const float* __restrict__ W_fc, const float* __restrict__ b_fc,
                             float* __restrict__ logitsOut, float* __restrict__ featsOut) {
    int b = blockIdx.x, n = threadIdx.x;
    const __half* hb = &g_hT[(size_t)b * HROW];
    float s = 0.f;
    #pragma unroll
    for (int hh = 1; hh <= 7; hh++)
        #pragma unroll
        for (int ww = 1; ww <= 7; ww++) s += __half2float(hb[(size_t)(hh * 9 + ww) * MEM_SZ + n]);
    float f = s * (1.0f / 49.0f);
    __shared__ float fs[MEM_SZ];
    fs[n] = f;
    if (featsOut) featsOut[b * MEM_SZ + n] = f;
    __syncthreads();
    if (n < N_CLS && logitsOut) {
        float acc = b_fc[n];
        for (int k = 0; k < MEM_SZ; k++) acc += fs[k] * W_fc[n * MEM_SZ + k];
        logitsOut[b * N_CLS + n] = acc;
    }
}

// ---------------------------------------------------------------------------
// Host launcher
// ---------------------------------------------------------------------------
extern "C" void kernel_launch(void* const* d_in, const int* in_sizes, int n_in,
                              void* d_out, int out_size) {
    const float* x     = (const float*)d_in[0];
    const float* W_fi  = (const float*)d_in[1];
    const float* b_fi  = (const float*)d_in[2];
    const float* W_c   = (const float*)d_in[3];
    const float* b_c   = (const float*)d_in[4];
    const float* W_o   = (const float*)d_in[5];
    const float* b_o   = (const float*)d_in[6];
    const float* Ws_fi = (const float*)d_in[7];
    const float* bs_fi = (const float*)d_in[8];
    const float* Ws_c  = (const float*)d_in[9];
    const float* bs_c  = (const float*)d_in[10];
    const float* Ws_o  = (const float*)d_in[11];
    const float* bs_o  = (const float*)d_in[12];
    const float* W_cam = (const float*)d_in[13];
    const float* W_fc  = (const float*)d_in[14];
    const float* b_fc  = (const float*)d_in[15];

    __half* xT; cudaGetSymbolAddress((void**)&xT, g_xT);
    __half* hT; cudaGetSymbolAddress((void**)&hT, g_hT);
    __half* wx; cudaGetSymbolAddress((void**)&wx, g_wx);
    __half* wh; cudaGetSymbolAddress((void**)&wh, g_wh);
    float*  pm; cudaGetSymbolAddress((void**)&pm, g_preM);
    float*  hp; cudaGetSymbolAddress((void**)&hp, g_hpre);

    const int SMEM_BYTES  = PIPE * STGB;    // 98304 (h-chain kernel)
    const int SMEM_BYTES2 = PIPE * STGB2;   // 147456 (big-M kernel)
    cudaFuncSetAttribute(conv_gemm_fp16, cudaFuncAttributeMaxDynamicSharedMemorySize, SMEM_BYTES);
    cudaFuncSetAttribute(conv_gemm_fp16_m256, cudaFuncAttributeMaxDynamicSharedMemorySize, SMEM_BYTES2);

    float* outF = (float*)d_out;
    float* lp = nullptr; float* fp = nullptr;
    if (out_size >= B_SZ * N_CLS + B_SZ * MEM_SZ) { lp = outF; fp = outF + B_SZ * N_CLS; }
    else if (out_size == B_SZ * MEM_SZ)           { fp = outF; }
    else                                          { lp = outF; }

    // 1. reset recurrent state (incl. g_hpre for skipped step-0 h-GEMM)
    zero_states<<<(MSTEP * NFUSED + 255) / 256, 256>>>();
    border_zero<<<(int)(((size_t)TB * 32 * C_IN + 255) / 256), 256>>>();
    // 2. transpose + pad input to fp16; reorder weights to fp16
    {
        dim3 grid(TB, C_IN / 32);
        pad_xT<<<grid, 256>>>(x);
    }
    reorder_wx<<<(int)(((size_t)3 * MEM_SZ * C_IN + 255) / 256), 256>>>(W_fi, W_c, W_o);
    reorder_wh<<<(int)(((size_t)3 * MEM_SZ * MEM_SZ + 255) / 256), 256>>>(W_fi, W_c, W_o);
    reorder_ws<<<(3 * C_IN + 255) / 256, 256>>>(Ws_fi, Ws_c, Ws_o);
    // 3. attention-gate x contributions
    preS_kernel<<<TB, 256>>>();
    // 4. CAM pipeline
    pooled_kernel<<<(TB * C_IN + 255) / 256, 256>>>(x);
    cam_logits_kernel<<<(TB * C_CAM + 3) / 4, 128>>>(W_cam);
    argmax_kernel<<<TB, 256>>>();
    cam_kernel<<<(TB * HW + 7) / 8, 256>>>(x, W_cam);
    cam_softmax_kernel<<<TB, 64>>>();
    // 5. fused attention recurrence
    att_fused<<<B_SZ, 64>>>(Ws_fi, Ws_c, Ws_o, bs_fi, bs_c, bs_o);
    // 6. attention scaling
    scale_x<<<(int)(((size_t)TB * HW * C_IN + 255) / 256), 256>>>();
    // 7. giant parallel GEMM (x part, all t, 3 gates) — big-M tile
    {
        dim3 grid(12, MBIG / 256);
        conv_gemm_fp16_m256<<<grid, 256, SMEM_BYTES2>>>(xT, C_IN, 11, MBIG, KX / 64, KX, wx, pm);
    }
    // 8. sequential main recurrence (t=0 h-GEMM skipped: h(0)=0, g_hpre zeroed)
    gate_step<<<(MSTEP * MEM_SZ + 255) / 256, 256>>>(0, b_fi, b_c, b_o);
    for (int t = 1; t < T_STEPS; t++) {
        dim3 grid(12, (MSTEP + 127) / 128);
        conv_gemm_fp16<<<grid, 256, SMEM_BYTES>>>(hT, MEM_SZ, 9, MSTEP, KH / 64, KH, wh, hp);
        gate_step<<<(MSTEP * MEM_SZ + 255) / 256, 256>>>(t, b_fi, b_c, b_o);
    }
    // 9. final pooling + FC head
    final_kernel<<<B_SZ, MEM_SZ>>>(W_fc, b_fc, lp, fp);
}